// round 11
// baseline (speedup 1.0000x reference)
#include <cuda_runtime.h>
#include <math.h>

#define NN 50000
#define EE 800000
#define F_STATS 1
#define F_BIAS  2
#define F_POOL  4
#define NTILES 391        // ceil(NN/128)
#define GRIDX  304        // 2 blocks/SM * 152 SMs -> single resident wave

// ------------------------- static device scratch (zero-init BSS) -------------------------
__device__ float g_stem[NN * 192];
__device__ float g_cell[2][NN * 256];
__device__ float g_ab[2][NN * 64];
__device__ float g_x0[NN * 64];
__device__ float g_tmp[NN * 192];
// derived per-state arrays: kind 0=mean, 1=sum, 2=norm, 3=h+sum, 4=norm+x0/9
__device__ float g_der[5][5][NN * 64];
__device__ float g_enorm[EE];
__device__ int   g_esrc[EE];
__device__ int   g_cnt[NN];
__device__ int   g_rptr[NN + 1];
__device__ int   g_fill[NN];
__device__ float g_invdeg[NN];
__device__ float g_invsqrt[NN];
__device__ float g_pooled[NN];
__device__ float g_colsum[256];
__device__ float g_colsq[256];
__device__ float g_mu[256];
__device__ float g_rsd[256];
__device__ float g_wmix[14 * 8];
__device__ float g_Wprep[28 * 7 * 4096];

// ------------------------- graph preprocessing -------------------------
__global__ void zero_cnt_kernel() {
    int i = blockIdx.x * blockDim.x + threadIdx.x;
    if (i < NN) g_cnt[i] = 0;
}

__global__ void deg_kernel(const int* __restrict__ dst) {
    int e = blockIdx.x * blockDim.x + threadIdx.x;
    if (e < EE) atomicAdd(&g_cnt[dst[e]], 1);
}

__global__ void scan_kernel() {
    __shared__ int sh[1024];
    int carry = 0;
    for (int base = 0; base < NN; base += 1024) {
        int i = base + (int)threadIdx.x;
        int v = (i < NN) ? g_cnt[i] : 0;
        sh[threadIdx.x] = v;
        __syncthreads();
        for (int off = 1; off < 1024; off <<= 1) {
            int t = (threadIdx.x >= off) ? sh[threadIdx.x - off] : 0;
            __syncthreads();
            sh[threadIdx.x] += t;
            __syncthreads();
        }
        int incl = sh[threadIdx.x];
        if (i < NN) {
            int excl = carry + incl - v;
            g_rptr[i] = excl;
            g_fill[i] = excl;
            float d = (float)(v > 0 ? v : 1);
            g_invdeg[i]  = 1.0f / d;
            g_invsqrt[i] = rsqrtf(d);
        }
        carry += sh[1023];
        __syncthreads();
    }
    if (threadIdx.x == 0) g_rptr[NN] = carry;
}

__global__ void scatter_kernel(const int* __restrict__ src, const int* __restrict__ dst) {
    int e = blockIdx.x * blockDim.x + threadIdx.x;
    if (e >= EE) return;
    int s = src[e], d = dst[e];
    int pos = atomicAdd(&g_fill[d], 1);
    g_esrc[pos]  = s;
    g_enorm[pos] = g_invsqrt[s] * g_invsqrt[d];
}

// ------------------------- alpha softmax + fused weight prep -------------------------
__global__ void softmax_kernel(const float* __restrict__ a) {
    int r = threadIdx.x;
    if (r >= 14) return;
    float m = -1e30f;
    for (int j = 0; j < 8; j++) m = fmaxf(m, a[r * 8 + j]);
    float e[8], s = 0.f;
    for (int j = 0; j < 8; j++) { e[j] = expf(a[r * 8 + j] - m); s += e[j]; }
    float inv = 1.f / s;
    for (int j = 0; j < 8; j++) g_wmix[r * 8 + j] = e[j] * inv;
}

__global__ void prep_kernel(const float* __restrict__ Wgcn, const float* __restrict__ Wss,
                            const float* __restrict__ Wsn,  const float* __restrict__ Wgin,
                            const float* __restrict__ Wgc1, const float* __restrict__ Wgc2,
                            const float* __restrict__ Wmlp, const float* __restrict__ Wgcnii) {
    int slot = blockIdx.x;                       // ci*14 + ej
    int ej   = slot % 14;
    int idx  = blockIdx.y * 256 + threadIdx.x;   // 0..4095
    int r = idx >> 6, c = idx & 63;
    const float* wv = g_wmix + ej * 8;
    size_t in = (size_t)slot * 4096 + idx;
    size_t ob = (size_t)slot * 7 * 4096;
    g_Wprep[ob + 0 * 4096 + idx] = wv[1] * (r == c ? 1.f : 0.f) + wv[3] * Wss[in] + wv[5] * Wgc1[in];
    g_Wprep[ob + 1 * 4096 + idx] = wv[3] * Wsn[in];
    g_Wprep[ob + 2 * 4096 + idx] = wv[5] * Wgc2[in];
    g_Wprep[ob + 3 * 4096 + idx] = wv[2] * Wgcn[in];
    g_Wprep[ob + 4 * 4096 + idx] = wv[4] * Wgin[in];
    g_Wprep[ob + 5 * 4096 + idx] = wv[6] * Wmlp[in];
    g_Wprep[ob + 6 * 4096 + idx] = wv[7] * 0.9f * Wgcnii[in];
}

// ------------------------- shared GEMM helpers (128x64 tile, 8x4 microtile) -------------------------

// full 64-k compute
__device__ __forceinline__ void gemm64(const float* __restrict__ Xs,
                                       const float* __restrict__ Ws,
                                       int ty8, int tx4, float (&acc)[8][4]) {
#pragma unroll 8
    for (int k = 0; k < 64; k++) {
        const float* xrow = Xs + k * 132 + ty8;
        float4 a0 = *(const float4*)(xrow);
        float4 a1 = *(const float4*)(xrow + 4);
        float4 b  = *(const float4*)&Ws[k * 64 + tx4];
        float ar[8] = {a0.x, a0.y, a0.z, a0.w, a1.x, a1.y, a1.z, a1.w};
        float br[4] = {b.x, b.y, b.z, b.w};
#pragma unroll
        for (int i = 0; i < 8; i++)
#pragma unroll
            for (int j = 0; j < 4; j++) acc[i][j] = fmaf(ar[i], br[j], acc[i][j]);
    }
}

// fill Xs[64][132] transposed from src rows [rowbase, rowbase+128), k = [kc, kc+64)
__device__ __forceinline__ void load_x64(const float* __restrict__ src, int ld,
                                         int rowbase, int kc, int tid, float* Xs) {
#pragma unroll
    for (int i = 0; i < 8; i++) {
        int idx = i * 256 + tid;        // 0..2047
        int row = idx >> 4, k4 = idx & 15;
        int gr = rowbase + row;
        float4 v = make_float4(0.f, 0.f, 0.f, 0.f);
        if (gr < NN) v = *(const float4*)&src[(size_t)gr * ld + kc + k4 * 4];
        int kb = k4 * 4;
        Xs[(kb + 0) * 132 + row] = v.x;
        Xs[(kb + 1) * 132 + row] = v.y;
        Xs[(kb + 2) * 132 + row] = v.z;
        Xs[(kb + 3) * 132 + row] = v.w;
    }
}

// load Ws[64][64] from row-major W (ld stride), zero-pad cols >= M
__device__ __forceinline__ void load_w64(const float* __restrict__ W, int ldw,
                                         int kc, int colbase, int M, int tid, float* Ws) {
#pragma unroll
    for (int i = 0; i < 4; i++) {
        int idx = i * 256 + tid;
        int kk = idx >> 4, c4 = (idx & 15) * 4;
        int gc = colbase + c4;
        float4 w4 = make_float4(0.f, 0.f, 0.f, 0.f);
        if (gc < M) w4 = *(const float4*)&W[(size_t)(kc + kk) * ldw + gc];
        *(float4*)&Ws[kk * 64 + c4] = w4;
    }
}

// ------------------------- generic fp32 linear (persistent row-tile loop) -------------------------
__global__ __launch_bounds__(256, 2)
void lin_kernel(const float* __restrict__ X, int ldx,
                const float* __restrict__ W, int ldw,
                float* __restrict__ Y, int ldy,
                int K, int M, int flags,
                const float* __restrict__ bias,
                const float* __restrict__ pooled,
                const float* __restrict__ w0) {
    __shared__ __align__(16) float Xs[64 * 132];
    __shared__ __align__(16) float Ws[64 * 64];
    int tid = threadIdx.x, tx = tid & 15, ty = tid >> 4;
    int colbase = blockIdx.y * 64;

    for (int t = blockIdx.x; t < NTILES; t += GRIDX) {
        int rowbase = t * 128;
        float acc[8][4];
#pragma unroll
        for (int i = 0; i < 8; i++)
#pragma unroll
            for (int j = 0; j < 4; j++) acc[i][j] = 0.f;

        for (int kc = 0; kc < K; kc += 64) {
            __syncthreads();
            load_w64(W, ldw, kc, colbase, M, tid, Ws);
            load_x64(X, ldx, rowbase, kc, tid, Xs);
            __syncthreads();
            gemm64(Xs, Ws, ty * 8, tx * 4, acc);
        }

        int r0 = rowbase + ty * 8, c0 = colbase + tx * 4;
#pragma unroll
        for (int i = 0; i < 8; i++) {
            int r = r0 + i;
            if (r >= NN) continue;
#pragma unroll
            for (int j = 0; j < 4; j++) {
                int c = c0 + j;
                if (c >= M) continue;
                float v = acc[i][j];
                if (flags & F_POOL) v = fmaf(pooled[r], w0[c], v);
                if (flags & F_BIAS) v += bias[c];
                Y[(size_t)r * ldy + c] = v;
            }
        }

        if (flags & F_STATS) {
            __syncthreads();
#pragma unroll
            for (int j = 0; j < 4; j++) {
                float s = 0.f, s2 = 0.f;
#pragma unroll
                for (int i = 0; i < 8; i++) {
                    int r = r0 + i;
                    if (r < NN) { float v = acc[i][j]; s += v; s2 = fmaf(v, v, s2); }
                }
                Xs[(tx * 4 + j) * 16 + ty] = s;
                Ws[(tx * 4 + j) * 16 + ty] = s2;
            }
            __syncthreads();
            if (tid < 64) {
                float s = 0.f, s2 = 0.f;
#pragma unroll
                for (int q = 0; q < 16; q++) { s += Xs[tid * 16 + q]; s2 += Ws[tid * 16 + q]; }
                int c = colbase + tid;
                if (c < M) { atomicAdd(&g_colsum[c], s); atomicAdd(&g_colsq[c], s2); }
            }
        }
    }
}

// ------------------------- batch norm helpers -------------------------
__global__ void zero_stats_kernel() {
    g_colsum[threadIdx.x] = 0.f;
    g_colsq[threadIdx.x]  = 0.f;
}

__global__ void bn_fin_kernel(int M) {
    int c = threadIdx.x;
    if (c >= M) return;
    float invN = 1.f / (float)NN;
    float mu  = g_colsum[c] * invN;
    float var = g_colsq[c] * invN - mu * mu;
    g_mu[c]  = mu;
    g_rsd[c] = rsqrtf(var + 1e-5f);
}

__global__ void bn_apply_kernel(const float* __restrict__ src, float* __restrict__ dst,
                                int total4, int M, int relu) {
    int i = blockIdx.x * blockDim.x + threadIdx.x;
    if (i >= total4) return;
    float4 v = ((const float4*)src)[i];
    int c = (i * 4) % M;
    v.x = (v.x - g_mu[c    ]) * g_rsd[c    ];
    v.y = (v.y - g_mu[c + 1]) * g_rsd[c + 1];
    v.z = (v.z - g_mu[c + 2]) * g_rsd[c + 2];
    v.w = (v.w - g_mu[c + 3]) * g_rsd[c + 3];
    if (relu) {
        v.x = fmaxf(v.x, 0.f); v.y = fmaxf(v.y, 0.f);
        v.z = fmaxf(v.z, 0.f); v.w = fmaxf(v.w, 0.f);
    }
    ((float4*)dst)[i] = v;
}

// ------------------------- CSR aggregation: writes 5 derived arrays -------------------------
__global__ void agg_kernel(const float* __restrict__ h, int ldh, int j) {
    int w = (blockIdx.x * blockDim.x + threadIdx.x) >> 5;
    int lane = threadIdx.x & 31;
    if (w >= NN) return;
    int beg = g_rptr[w], end = g_rptr[w + 1];
    float sx = 0.f, sy = 0.f, nx = 0.f, ny = 0.f;
    for (int e = beg; e < end; e++) {
        int s = g_esrc[e];
        float wn = g_enorm[e];
        float2 v = *(const float2*)&h[(size_t)s * ldh + lane * 2];
        sx += v.x; sy += v.y;
        nx = fmaf(wn, v.x, nx); ny = fmaf(wn, v.y, ny);
    }
    float2 hv = *(const float2*)&h[(size_t)w * ldh + lane * 2];
    float2 xv = *(const float2*)&g_x0[(size_t)w * 64 + lane * 2];
    float id = g_invdeg[w];
    size_t o = (size_t)w * 64 + lane * 2;
    *(float2*)&g_der[0][j][o] = make_float2(sx * id, sy * id);                    // mean
    *(float2*)&g_der[1][j][o] = make_float2(sx, sy);                              // sum
    *(float2*)&g_der[2][j][o] = make_float2(nx, ny);                              // norm
    *(float2*)&g_der[3][j][o] = make_float2(hv.x + sx, hv.y + sy);                // h+sum
    *(float2*)&g_der[4][j][o] = make_float2(fmaf(0.11111111f, xv.x, nx),
                                            fmaf(0.11111111f, xv.y, ny));         // norm+x0/9
}

// ------------------------- fused per-step mixed-op -------------------------
struct StepArgs {
    const float* h[5];
    int ldh[5];
    const float* wbase;
    float* out;     // ld 256, 64-col slice
    int nst;
};

__global__ __launch_bounds__(256, 2)
void step_kernel(StepArgs A) {
    __shared__ __align__(16) float Xs[64 * 132];
    __shared__ __align__(16) float Ws[64 * 64];
    int tid = threadIdx.x, tx = tid & 15, ty = tid >> 4;
    int ty8 = ty * 8, tx4 = tx * 4;
    // pass order: relu passes (3,4,6,5) then linear (0,1,2); p5 and p0 share X=h fill
    const int order[7] = {3, 4, 6, 5, 0, 1, 2};

    for (int t = blockIdx.x; t < NTILES; t += GRIDX) {
        int rowbase = t * 128;
        float acc[8][4];
#pragma unroll
        for (int i = 0; i < 8; i++)
#pragma unroll
            for (int j = 0; j < 4; j++) acc[i][j] = 0.f;

        for (int j = 0; j < A.nst; j++) {
            const float* hj = A.h[j];
            int ldh = A.ldh[j];
            const float* wj = A.wbase + (size_t)j * 7 * 4096;

#pragma unroll 1
            for (int oi = 0; oi < 7; oi++) {
                int p = order[oi];
                const float* src;
                int ld;
                switch (p) {
                    case 0:  src = hj;              ld = ldh; break;  // merged linear on h
                    case 1:  src = &g_der[0][j][0]; ld = 64;  break;  // mean
                    case 2:  src = &g_der[1][j][0]; ld = 64;  break;  // sum
                    case 3:  src = &g_der[2][j][0]; ld = 64;  break;  // norm (gcn)
                    case 4:  src = &g_der[3][j][0]; ld = 64;  break;  // h+sum (gin)
                    case 5:  src = hj;              ld = ldh; break;  // h (mlp)
                    default: src = &g_der[4][j][0]; ld = 64;  break;  // norm+x0/9 (gcnii)
                }
                __syncthreads();
                load_w64(wj + (size_t)p * 4096, 64, 0, 0, 64, tid, Ws);
                if (oi != 4)  // oi==4 (p0) reuses the h tile filled at oi==3 (p5)
                    load_x64(src, ld, rowbase, 0, tid, Xs);
                __syncthreads();

                if (oi < 4) {  // relu pass
                    float pacc[8][4];
#pragma unroll
                    for (int i = 0; i < 8; i++)
#pragma unroll
                        for (int q = 0; q < 4; q++) pacc[i][q] = 0.f;
                    gemm64(Xs, Ws, ty8, tx4, pacc);
#pragma unroll
                    for (int i = 0; i < 8; i++)
#pragma unroll
                        for (int q = 0; q < 4; q++) acc[i][q] += fmaxf(pacc[i][q], 0.f);
                } else {       // linear pass: accumulate directly
                    gemm64(Xs, Ws, ty8, tx4, acc);
                }
            }
        }

        int r0 = rowbase + ty8;
#pragma unroll
        for (int i = 0; i < 8; i++) {
            int r = r0 + i;
            if (r < NN)
                *(float4*)&A.out[(size_t)r * 256 + tx4] =
                    make_float4(acc[i][0], acc[i][1], acc[i][2], acc[i][3]);
        }
    }
}

// ------------------------- channel mean pooling -------------------------
__global__ void pooled_kernel(const float* __restrict__ h) {
    int w = (blockIdx.x * blockDim.x + threadIdx.x) >> 5;
    int lane = threadIdx.x & 31;
    if (w >= NN) return;
    const float* row = h + (size_t)w * 256;
    float s = 0.f;
#pragma unroll
    for (int i = 0; i < 8; i++) s += row[lane + i * 32];
#pragma unroll
    for (int off = 16; off > 0; off >>= 1) s += __shfl_xor_sync(0xffffffff, s, off);
    if (lane == 0) g_pooled[w] = s * (1.f / 256.f);
}

// ------------------------- host orchestration -------------------------
extern "C" void kernel_launch(void* const* d_in, const int* in_sizes, int n_in,
                              void* d_out, int out_size) {
    const float* x      = (const float*)d_in[0];
    const int*   ei     = (const int*)d_in[1];
    const float* alphas = (const float*)d_in[2];
    const float* stem_W = (const float*)d_in[3];
    const float* pre_W  = (const float*)d_in[4];
    const float* pre00  = (const float*)d_in[5];
    const float* pre10  = (const float*)d_in[6];
    const float* pre01  = (const float*)d_in[7];
    const float* pre11  = (const float*)d_in[8];
    const float* cls_W  = (const float*)d_in[17];
    const float* cls_b  = (const float*)d_in[18];
    float* out = (float*)d_out;

    float *stem, *cell, *ab, *x0p, *tmp, *prep, *pooledb;
    cudaGetSymbolAddress((void**)&stem,    g_stem);
    cudaGetSymbolAddress((void**)&cell,    g_cell);
    cudaGetSymbolAddress((void**)&ab,      g_ab);
    cudaGetSymbolAddress((void**)&x0p,     g_x0);
    cudaGetSymbolAddress((void**)&tmp,     g_tmp);
    cudaGetSymbolAddress((void**)&prep,    g_Wprep);
    cudaGetSymbolAddress((void**)&pooledb, g_pooled);
    float* cell0 = cell;
    float* cell1 = cell + (size_t)NN * 256;
    float* ab0 = ab;
    float* ab1 = ab + (size_t)NN * 64;

    // graph preprocessing
    zero_cnt_kernel<<<(NN + 255) / 256, 256>>>();
    deg_kernel<<<(EE + 255) / 256, 256>>>(ei + EE);
    scan_kernel<<<1, 1024>>>();
    scatter_kernel<<<(EE + 255) / 256, 256>>>(ei, ei + EE);

    // mixed-op weight prep
    softmax_kernel<<<1, 32>>>(alphas);
    prep_kernel<<<dim3(28, 16), 256>>>((const float*)d_in[9],  (const float*)d_in[10],
                                       (const float*)d_in[11], (const float*)d_in[12],
                                       (const float*)d_in[13], (const float*)d_in[14],
                                       (const float*)d_in[15], (const float*)d_in[16]);

    auto LIN = [&](const float* X, int ldx, const float* W, int ldw, float* Y, int ldy,
                   int K, int M, int flags, const float* bias, const float* pooled,
                   const float* w0) {
        dim3 grid(GRIDX, (M + 63) / 64);
        lin_kernel<<<grid, 256>>>(X, ldx, W, ldw, Y, ldy, K, M, flags, bias, pooled, w0);
    };
    auto BNL = [&](const float* X, int ldx, const float* W, float* dst, int K, int M, int relu) {
        zero_stats_kernel<<<1, 256>>>();
        LIN(X, ldx, W, M, tmp, M, K, M, F_STATS, nullptr, nullptr, nullptr);
        bn_fin_kernel<<<1, 256>>>(M);
        int t4 = NN * M / 4;
        bn_apply_kernel<<<(t4 + 255) / 256, 256>>>(tmp, dst, t4, M, relu);
    };

    BNL(x, 128, stem_W, stem, 128, 192, 0);   // stem [N,192], no relu
    BNL(x, 128, pre_W,  x0p,  128, 64, 1);    // x0 [N,64], relu

    const int AGGB = (NN * 32 + 255) / 256;   // warp per node
    for (int ci = 0; ci < 2; ci++) {
        const float* p0 = ci ? pre01 : pre00;
        const float* p1 = ci ? pre11 : pre10;
        const float* s1p = ci ? cell0 : stem;
        int lds1 = ci ? 256 : 192;
        float* co = ci ? cell1 : cell0;

        BNL(stem, 192, p0, ab0, 192, 64, 1);
        BNL(s1p, lds1, p1, ab1, lds1, 64, 1);

        auto stptr = [&](int j) -> float* { return j == 0 ? ab0 : (j == 1 ? ab1 : co + (j - 2) * 64); };
        auto stld  = [&](int j) -> int    { return j < 2 ? 64 : 256; };

        agg_kernel<<<AGGB, 256>>>(stptr(0), 64, 0);
        agg_kernel<<<AGGB, 256>>>(stptr(1), 64, 1);

        int offset = 0;
        for (int step = 0; step < 4; step++) {
            int nst = 2 + step;
            if (step > 0) {
                int jn = nst - 1;  // newest state (2,3,4)
                agg_kernel<<<AGGB, 256>>>(stptr(jn), stld(jn), jn);
            }
            StepArgs A;
            for (int j = 0; j < nst; j++) { A.h[j] = stptr(j); A.ldh[j] = stld(j); }
            for (int j = nst; j < 5; j++) { A.h[j] = stptr(0); A.ldh[j] = 64; }
            A.wbase = prep + (size_t)(ci * 14 + offset) * 7 * 4096;
            A.out   = stptr(nst);
            A.nst   = nst;
            step_kernel<<<GRIDX, 256>>>(A);
            offset += nst;
        }
    }

    // classifier: logits = pooled*cls_W[0] + s1 @ cls_W[1:] + b
    pooled_kernel<<<AGGB, 256>>>(cell1);
    LIN(cell1, 256, cls_W + 40, 40, out, 40, 256, 40, F_POOL | F_BIAS, cls_b, pooledb, cls_W);
}

// round 13
// speedup vs baseline: 1.2026x; 1.2026x over previous
#include <cuda_runtime.h>
#include <math.h>
#include <stdint.h>

#define NN 50000
#define EE 800000
#define F_STATS 1
#define F_BIAS  2
#define F_POOL  4
#define GR 391            // ceil(NN/128)

// ------------------------- static device scratch (zero-init BSS) -------------------------
__device__ float g_stem[NN * 192];
__device__ float g_cell[2][NN * 256];
__device__ float g_ab[2][NN * 64];
__device__ float g_x0[NN * 64];
__device__ float g_tmp[NN * 192];
// derived per-state arrays: kind 0=mean, 1=sum, 2=norm, 3=h+sum, 4=norm+x0/9
__device__ float g_der[5][5][NN * 64];
__device__ float g_enorm[EE];
__device__ int   g_esrc[EE];
__device__ int   g_cnt[NN];
__device__ int   g_rptr[NN + 1];
__device__ int   g_fill[NN];
__device__ float g_invdeg[NN];
__device__ float g_invsqrt[NN];
__device__ float g_pooled[NN];
__device__ float g_colsum[256];
__device__ float g_colsq[256];
__device__ float g_mu[256];
__device__ float g_rsd[256];
__device__ float g_wmix[14 * 8];
// fused mixed-op weights in m16n8k8 B-fragment order: per (slot,pass,frag,lane) = {b0hi,b1hi,b0lo,b1lo}
__device__ float4 g_Wfrag[28 * 7 * 64 * 32];

__device__ __forceinline__ float tf32r(float x) {
    uint32_t u;
    asm("cvt.rna.tf32.f32 %0, %1;" : "=r"(u) : "f"(x));
    return __uint_as_float(u);
}
__device__ __forceinline__ void mma8(float (&d)[4], uint32_t a0, uint32_t a1, uint32_t a2,
                                     uint32_t a3, uint32_t b0, uint32_t b1) {
    asm volatile("mma.sync.aligned.m16n8k8.row.col.f32.tf32.tf32.f32 "
                 "{%0,%1,%2,%3}, {%4,%5,%6,%7}, {%8,%9}, {%0,%1,%2,%3};"
                 : "+f"(d[0]), "+f"(d[1]), "+f"(d[2]), "+f"(d[3])
                 : "r"(a0), "r"(a1), "r"(a2), "r"(a3), "r"(b0), "r"(b1));
}

// ------------------------- graph preprocessing -------------------------
__global__ void zero_cnt_kernel() {
    int i = blockIdx.x * blockDim.x + threadIdx.x;
    if (i < NN) g_cnt[i] = 0;
}

__global__ void deg_kernel(const int* __restrict__ dst) {
    int e = blockIdx.x * blockDim.x + threadIdx.x;
    if (e < EE) atomicAdd(&g_cnt[dst[e]], 1);
}

__global__ void scan_kernel() {
    __shared__ int sh[1024];
    int carry = 0;
    for (int base = 0; base < NN; base += 1024) {
        int i = base + (int)threadIdx.x;
        int v = (i < NN) ? g_cnt[i] : 0;
        sh[threadIdx.x] = v;
        __syncthreads();
        for (int off = 1; off < 1024; off <<= 1) {
            int t = (threadIdx.x >= off) ? sh[threadIdx.x - off] : 0;
            __syncthreads();
            sh[threadIdx.x] += t;
            __syncthreads();
        }
        int incl = sh[threadIdx.x];
        if (i < NN) {
            int excl = carry + incl - v;
            g_rptr[i] = excl;
            g_fill[i] = excl;
            float d = (float)(v > 0 ? v : 1);
            g_invdeg[i]  = 1.0f / d;
            g_invsqrt[i] = rsqrtf(d);
        }
        carry += sh[1023];
        __syncthreads();
    }
    if (threadIdx.x == 0) g_rptr[NN] = carry;
}

__global__ void scatter_kernel(const int* __restrict__ src, const int* __restrict__ dst) {
    int e = blockIdx.x * blockDim.x + threadIdx.x;
    if (e >= EE) return;
    int s = src[e], d = dst[e];
    int pos = atomicAdd(&g_fill[d], 1);
    g_esrc[pos]  = s;
    g_enorm[pos] = g_invsqrt[s] * g_invsqrt[d];
}

// ------------------------- alpha softmax + fragment-order weight prep ----------------------
__global__ void softmax_kernel(const float* __restrict__ a) {
    int r = threadIdx.x;
    if (r >= 14) return;
    float m = -1e30f;
    for (int j = 0; j < 8; j++) m = fmaxf(m, a[r * 8 + j]);
    float e[8], s = 0.f;
    for (int j = 0; j < 8; j++) { e[j] = expf(a[r * 8 + j] - m); s += e[j]; }
    float inv = 1.f / s;
    for (int j = 0; j < 8; j++) g_wmix[r * 8 + j] = e[j] * inv;
}

__global__ void prep_kernel(const float* __restrict__ Wgcn, const float* __restrict__ Wss,
                            const float* __restrict__ Wsn,  const float* __restrict__ Wgin,
                            const float* __restrict__ Wgc1, const float* __restrict__ Wgc2,
                            const float* __restrict__ Wmlp, const float* __restrict__ Wgcnii) {
    int slot = blockIdx.x;    // ci*14 + ej
    int p    = blockIdx.y;    // pass 0..6
    int ej   = slot % 14;
    const float* wv = g_wmix + ej * 8;

    auto fused = [&](int k, int n) -> float {
        size_t in = (size_t)slot * 4096 + k * 64 + n;
        switch (p) {
            case 0:  return wv[1] * (k == n ? 1.f : 0.f) + wv[3] * Wss[in] + wv[5] * Wgc1[in];
            case 1:  return wv[3] * Wsn[in];
            case 2:  return wv[5] * Wgc2[in];
            case 3:  return wv[2] * Wgcn[in];
            case 4:  return wv[4] * Wgin[in];
            case 5:  return wv[6] * Wmlp[in];
            default: return wv[7] * 0.9f * Wgcnii[in];
        }
    };

    for (int i = 0; i < 8; i++) {
        int item = i * 256 + threadIdx.x;   // 0..2047
        int frag = item >> 5, lane = item & 31;
        int ks = frag >> 3, nt = frag & 7;
        int g = lane >> 2, t = lane & 3;
        int k0 = ks * 8 + t, k1 = k0 + 4, n = nt * 8 + g;
        float v0 = fused(k0, n), v1 = fused(k1, n);
        float h0 = tf32r(v0), h1 = tf32r(v1);
        g_Wfrag[(((size_t)slot * 7 + p) * 64 + frag) * 32 + lane] =
            make_float4(h0, h1, v0 - h0, v1 - h1);
    }
}

// ------------------------- scalar fp32 linear (R8-proven) -------------------------
__global__ __launch_bounds__(256)
void lin_kernel(const float* __restrict__ X, int ldx,
                const float* __restrict__ W, int ldw,
                float* __restrict__ Y, int ldy,
                int K, int M, int flags,
                const float* __restrict__ bias,
                const float* __restrict__ pooled,
                const float* __restrict__ w0) {
    __shared__ __align__(16) float Xs[32 * 132];
    __shared__ __align__(16) float Ws[32 * 64];
    int tid = threadIdx.x, tx = tid & 15, ty = tid >> 4;
    int rowbase = blockIdx.x * 128, colbase = blockIdx.y * 64;
    float acc[8][4];
#pragma unroll
    for (int i = 0; i < 8; i++)
#pragma unroll
        for (int j = 0; j < 4; j++) acc[i][j] = 0.f;

    for (int kc = 0; kc < K; kc += 32) {
        __syncthreads();
#pragma unroll
        for (int i = 0; i < 2; i++) {
            int idx = i * 256 + tid;
            int kk = idx >> 4, c4 = (idx & 15) * 4;
            int gc = colbase + c4;
            float4 w4 = make_float4(0.f, 0.f, 0.f, 0.f);
            if (gc < M) w4 = *(const float4*)&W[(size_t)(kc + kk) * ldw + gc];
            *(float4*)&Ws[kk * 64 + c4] = w4;
        }
#pragma unroll
        for (int i = 0; i < 4; i++) {
            int idx = i * 256 + tid;
            int row = idx >> 3, k4 = idx & 7;
            int gr = rowbase + row;
            float4 v = make_float4(0.f, 0.f, 0.f, 0.f);
            if (gr < NN) v = *(const float4*)&X[(size_t)gr * ldx + kc + k4 * 4];
            int kb = k4 * 4;
            Xs[(kb + 0) * 132 + row] = v.x;
            Xs[(kb + 1) * 132 + row] = v.y;
            Xs[(kb + 2) * 132 + row] = v.z;
            Xs[(kb + 3) * 132 + row] = v.w;
        }
        __syncthreads();
#pragma unroll 8
        for (int k = 0; k < 32; k++) {
            float4 a0 = *(const float4*)&Xs[k * 132 + ty * 8];
            float4 a1 = *(const float4*)&Xs[k * 132 + ty * 8 + 4];
            float4 b  = *(const float4*)&Ws[k * 64 + tx * 4];
            float ar[8] = {a0.x, a0.y, a0.z, a0.w, a1.x, a1.y, a1.z, a1.w};
            float br[4] = {b.x, b.y, b.z, b.w};
#pragma unroll
            for (int i = 0; i < 8; i++)
#pragma unroll
                for (int j = 0; j < 4; j++) acc[i][j] = fmaf(ar[i], br[j], acc[i][j]);
        }
    }

    int r0 = rowbase + ty * 8, c0 = colbase + tx * 4;
#pragma unroll
    for (int i = 0; i < 8; i++) {
        int r = r0 + i;
        if (r >= NN) continue;
#pragma unroll
        for (int j = 0; j < 4; j++) {
            int c = c0 + j;
            if (c >= M) continue;
            float v = acc[i][j];
            if (flags & F_POOL) v = fmaf(pooled[r], w0[c], v);
            if (flags & F_BIAS) v += bias[c];
            Y[(size_t)r * ldy + c] = v;
        }
    }

    if (flags & F_STATS) {
        __syncthreads();
#pragma unroll
        for (int j = 0; j < 4; j++) {
            float s = 0.f, s2 = 0.f;
#pragma unroll
            for (int i = 0; i < 8; i++) {
                int r = r0 + i;
                if (r < NN) { float v = acc[i][j]; s += v; s2 = fmaf(v, v, s2); }
            }
            Xs[(tx * 4 + j) * 16 + ty] = s;
            Ws[(tx * 4 + j) * 16 + ty] = s2;
        }
        __syncthreads();
        if (tid < 64) {
            float s = 0.f, s2 = 0.f;
#pragma unroll
            for (int t = 0; t < 16; t++) { s += Xs[tid * 16 + t]; s2 += Ws[tid * 16 + t]; }
            int c = colbase + tid;
            if (c < M) { atomicAdd(&g_colsum[c], s); atomicAdd(&g_colsq[c], s2); }
        }
    }
}

// ------------------------- batch norm helpers -------------------------
__global__ void zero_stats_kernel() {
    g_colsum[threadIdx.x] = 0.f;
    g_colsq[threadIdx.x]  = 0.f;
}

__global__ void bn_fin_kernel(int M) {
    int c = threadIdx.x;
    if (c >= M) return;
    float invN = 1.f / (float)NN;
    float mu  = g_colsum[c] * invN;
    float var = g_colsq[c] * invN - mu * mu;
    g_mu[c]  = mu;
    g_rsd[c] = rsqrtf(var + 1e-5f);
}

__global__ void bn_apply_kernel(const float* __restrict__ src, float* __restrict__ dst,
                                int total4, int M, int relu) {
    int i = blockIdx.x * blockDim.x + threadIdx.x;
    if (i >= total4) return;
    float4 v = ((const float4*)src)[i];
    int c = (i * 4) % M;
    v.x = (v.x - g_mu[c    ]) * g_rsd[c    ];
    v.y = (v.y - g_mu[c + 1]) * g_rsd[c + 1];
    v.z = (v.z - g_mu[c + 2]) * g_rsd[c + 2];
    v.w = (v.w - g_mu[c + 3]) * g_rsd[c + 3];
    if (relu) {
        v.x = fmaxf(v.x, 0.f); v.y = fmaxf(v.y, 0.f);
        v.z = fmaxf(v.z, 0.f); v.w = fmaxf(v.w, 0.f);
    }
    ((float4*)dst)[i] = v;
}

// ------------------------- CSR aggregation: writes 5 derived arrays -------------------------
__global__ void agg_kernel(const float* __restrict__ h, int ldh, int j) {
    int w = (blockIdx.x * blockDim.x + threadIdx.x) >> 5;
    int lane = threadIdx.x & 31;
    if (w >= NN) return;
    int beg = g_rptr[w], end = g_rptr[w + 1];
    float sx = 0.f, sy = 0.f, nx = 0.f, ny = 0.f;
    for (int e = beg; e < end; e++) {
        int s = g_esrc[e];
        float wn = g_enorm[e];
        float2 v = *(const float2*)&h[(size_t)s * ldh + lane * 2];
        sx += v.x; sy += v.y;
        nx = fmaf(wn, v.x, nx); ny = fmaf(wn, v.y, ny);
    }
    float2 hv = *(const float2*)&h[(size_t)w * ldh + lane * 2];
    float2 xv = *(const float2*)&g_x0[(size_t)w * 64 + lane * 2];
    float id = g_invdeg[w];
    size_t o = (size_t)w * 64 + lane * 2;
    *(float2*)&g_der[0][j][o] = make_float2(sx * id, sy * id);
    *(float2*)&g_der[1][j][o] = make_float2(sx, sy);
    *(float2*)&g_der[2][j][o] = make_float2(nx, ny);
    *(float2*)&g_der[3][j][o] = make_float2(hv.x + sx, hv.y + sy);
    *(float2*)&g_der[4][j][o] = make_float2(fmaf(0.11111111f, xv.x, nx),
                                            fmaf(0.11111111f, xv.y, ny));
}

// ------------------------- tensor-core (mma.sync tf32 x3) fused per-step mixed-op ----------
struct StepArgsM {
    const float* h[5];
    int ldh[5];
    const float4* wfrag;   // base for this step's first slot: (slotbase*7*64*32)
    float* out;            // ld 256, 64-col slice
    int nst;
};

#define XS_FLOATS (128 * 68)
#define SMEM_MMA  ((XS_FLOATS + 64 * 32 * 4) * 4)

__global__ __launch_bounds__(256)
void step_mma(StepArgsM A) {
    extern __shared__ __align__(16) float sm[];
    float*  Xs = sm;
    float4* Wf = (float4*)(sm + XS_FLOATS);
    int tid = threadIdx.x, lane = tid & 31, wid = tid >> 5;
    int wm = wid & 3, wn = wid >> 2;       // warp tile: rows wm*32..+32, cols wn*32..+32
    int g = lane >> 2, t = lane & 3;
    int rowbase = blockIdx.x * 128;
    const int order[7] = {3, 4, 6, 5, 0, 1, 2};

    float acc[32];
#pragma unroll
    for (int i = 0; i < 32; i++) acc[i] = 0.f;

    for (int j = 0; j < A.nst; j++) {
        const float* hj = A.h[j];
        int ldh = A.ldh[j];
        const float4* wj = A.wfrag + (size_t)j * 7 * 2048;

#pragma unroll 1
        for (int oi = 0; oi < 7; oi++) {
            int p = order[oi];
            const float* src;
            int ld;
            switch (p) {
                case 0:  src = hj;              ld = ldh; break;
                case 1:  src = &g_der[0][j][0]; ld = 64;  break;
                case 2:  src = &g_der[1][j][0]; ld = 64;  break;
                case 3:  src = &g_der[2][j][0]; ld = 64;  break;
                case 4:  src = &g_der[3][j][0]; ld = 64;  break;
                case 5:  src = hj;              ld = ldh; break;
                default: src = &g_der[4][j][0]; ld = 64;  break;
            }
            __syncthreads();
            // W fragments: straight copy (already fragment-ordered hi/lo)
            {
                const float4* wsrc = wj + (size_t)p * 2048;
#pragma unroll
                for (int i = 0; i < 8; i++) Wf[i * 256 + tid] = wsrc[i * 256 + tid];
            }
            // X tile: plain row-major [128][68]  (oi==4 reuses oi==3's h tile)
            if (oi != 4) {
#pragma unroll
                for (int i = 0; i < 8; i++) {
                    int idx = i * 256 + tid;
                    int row = idx >> 4, c4 = idx & 15;
                    int gr = rowbase + row;
                    float4 v = make_float4(0.f, 0.f, 0.f, 0.f);
                    if (gr < NN) v = *(const float4*)&src[(size_t)gr * ld + c4 * 4];
                    *(float4*)&Xs[row * 68 + c4 * 4] = v;
                }
            }
            __syncthreads();

            float pacc[32];
#pragma unroll
            for (int i = 0; i < 32; i++) pacc[i] = 0.f;

#pragma unroll
            for (int ks = 0; ks < 8; ks++) {
                uint32_t ahi[2][4], alo[2][4];
#pragma unroll
                for (int mt = 0; mt < 2; mt++) {
                    int base = (wm * 32 + mt * 16 + g) * 68 + ks * 8 + t;
                    float a0 = Xs[base];
                    float a1 = Xs[base + 8 * 68];
                    float a2 = Xs[base + 4];
                    float a3 = Xs[base + 8 * 68 + 4];
                    float h0 = tf32r(a0), h1 = tf32r(a1), h2 = tf32r(a2), h3 = tf32r(a3);
                    ahi[mt][0] = __float_as_uint(h0); alo[mt][0] = __float_as_uint(a0 - h0);
                    ahi[mt][1] = __float_as_uint(h1); alo[mt][1] = __float_as_uint(a1 - h1);
                    ahi[mt][2] = __float_as_uint(h2); alo[mt][2] = __float_as_uint(a2 - h2);
                    ahi[mt][3] = __float_as_uint(h3); alo[mt][3] = __float_as_uint(a3 - h3);
                }
#pragma unroll
                for (int nt = 0; nt < 4; nt++) {
                    float4 b = Wf[(ks * 8 + wn * 4 + nt) * 32 + lane];
                    uint32_t b0h = __float_as_uint(b.x), b1h = __float_as_uint(b.y);
                    uint32_t b0l = __float_as_uint(b.z), b1l = __float_as_uint(b.w);
#pragma unroll
                    for (int mt = 0; mt < 2; mt++) {
                        float (&d)[4] = *(float (*)[4])&pacc[(mt * 4 + nt) * 4];
                        mma8(d, ahi[mt][0], ahi[mt][1], ahi[mt][2], ahi[mt][3], b0h, b1h);
                        mma8(d, alo[mt][0], alo[mt][1], alo[mt][2], alo[mt][3], b0h, b1h);
                        mma8(d, ahi[mt][0], ahi[mt][1], ahi[mt][2], ahi[mt][3], b0l, b1l);
                    }
                }
            }
            if (oi < 4) {
#pragma unroll
                for (int i = 0; i < 32; i++) acc[i] += fmaxf(pacc[i], 0.f);
            } else {
#pragma unroll
                for (int i = 0; i < 32; i++) acc[i] += pacc[i];
            }
        }
    }

    // store: C fragment layout
#pragma unroll
    for (int mt = 0; mt < 2; mt++)
#pragma unroll
        for (int nt = 0; nt < 4; nt++) {
            const float* a = &acc[(mt * 4 + nt) * 4];
            int row0 = rowbase + wm * 32 + mt * 16 + g;
            int col  = wn * 32 + nt * 8 + t * 2;
            if (row0 < NN)
                *(float2*)&A.out[(size_t)row0 * 256 + col] = make_float2(a[0], a[1]);
            int row1 = row0 + 8;
            if (row1 < NN)
                *(float2*)&A.out[(size_t)row1 * 256 + col] = make_float2(a[2], a[3]);
        }
}

// ------------------------- channel mean pooling -------------------------
__global__ void pooled_kernel(const float* __restrict__ h) {
    int w = (blockIdx.x * blockDim.x + threadIdx.x) >> 5;
    int lane = threadIdx.x & 31;
    if (w >= NN) return;
    const float* row = h + (size_t)w * 256;
    float s = 0.f;
#pragma unroll
    for (int i = 0; i < 8; i++) s += row[lane + i * 32];
#pragma unroll
    for (int off = 16; off > 0; off >>= 1) s += __shfl_xor_sync(0xffffffff, s, off);
    if (lane == 0) g_pooled[w] = s * (1.f / 256.f);
}

// ------------------------- host orchestration -------------------------
extern "C" void kernel_launch(void* const* d_in, const int* in_sizes, int n_in,
                              void* d_out, int out_size) {
    const float* x      = (const float*)d_in[0];
    const int*   ei     = (const int*)d_in[1];
    const float* alphas = (const float*)d_in[2];
    const float* stem_W = (const float*)d_in[3];
    const float* pre_W  = (const float*)d_in[4];
    const float* pre00  = (const float*)d_in[5];
    const float* pre10  = (const float*)d_in[6];
    const float* pre01  = (const float*)d_in[7];
    const float* pre11  = (const float*)d_in[8];
    const float* cls_W  = (const float*)d_in[17];
    const float* cls_b  = (const float*)d_in[18];
    float* out = (float*)d_out;

    float *stem, *cell, *ab, *x0p, *tmp, *pooledb;
    float4* wfrag;
    cudaGetSymbolAddress((void**)&stem,    g_stem);
    cudaGetSymbolAddress((void**)&cell,    g_cell);
    cudaGetSymbolAddress((void**)&ab,      g_ab);
    cudaGetSymbolAddress((void**)&x0p,     g_x0);
    cudaGetSymbolAddress((void**)&tmp,     g_tmp);
    cudaGetSymbolAddress((void**)&wfrag,   g_Wfrag);
    cudaGetSymbolAddress((void**)&pooledb, g_pooled);
    float* cell0 = cell;
    float* cell1 = cell + (size_t)NN * 256;
    float* ab0 = ab;
    float* ab1 = ab + (size_t)NN * 64;

    cudaFuncSetAttribute(step_mma, cudaFuncAttributeMaxDynamicSharedMemorySize, SMEM_MMA);

    // graph preprocessing
    zero_cnt_kernel<<<(NN + 255) / 256, 256>>>();
    deg_kernel<<<(EE + 255) / 256, 256>>>(ei + EE);
    scan_kernel<<<1, 1024>>>();
    scatter_kernel<<<(EE + 255) / 256, 256>>>(ei, ei + EE);

    // mixed-op weight prep (fused + fragment-ordered + hi/lo split)
    softmax_kernel<<<1, 32>>>(alphas);
    prep_kernel<<<dim3(28, 7), 256>>>((const float*)d_in[9],  (const float*)d_in[10],
                                      (const float*)d_in[11], (const float*)d_in[12],
                                      (const float*)d_in[13], (const float*)d_in[14],
                                      (const float*)d_in[15], (const float*)d_in[16]);

    auto LIN = [&](const float* X, int ldx, const float* W, int ldw, float* Y, int ldy,
                   int K, int M, int flags, const float* bias, const float* pooled,
                   const float* w0) {
        dim3 grid(GR, (M + 63) / 64);
        lin_kernel<<<grid, 256>>>(X, ldx, W, ldw, Y, ldy, K, M, flags, bias, pooled, w0);
    };
    auto BNL = [&](const float* X, int ldx, const float* W, float* dst, int K, int M, int relu) {
        zero_stats_kernel<<<1, 256>>>();
        LIN(X, ldx, W, M, tmp, M, K, M, F_STATS, nullptr, nullptr, nullptr);
        bn_fin_kernel<<<1, 256>>>(M);
        int t4 = NN * M / 4;
        bn_apply_kernel<<<(t4 + 255) / 256, 256>>>(tmp, dst, t4, M, relu);
    };

    BNL(x, 128, stem_W, stem, 128, 192, 0);   // stem [N,192], no relu
    BNL(x, 128, pre_W,  x0p,  128, 64, 1);    // x0 [N,64], relu

    const int AGGB = (NN * 32 + 255) / 256;   // warp per node
    for (int ci = 0; ci < 2; ci++) {
        const float* p0 = ci ? pre01 : pre00;
        const float* p1 = ci ? pre11 : pre10;
        const float* s1p = ci ? cell0 : stem;
        int lds1 = ci ? 256 : 192;
        float* co = ci ? cell1 : cell0;

        BNL(stem, 192, p0, ab0, 192, 64, 1);
        BNL(s1p, lds1, p1, ab1, lds1, 64, 1);

        auto stptr = [&](int j) -> float* { return j == 0 ? ab0 : (j == 1 ? ab1 : co + (j - 2) * 64); };
        auto stld  = [&](int j) -> int    { return j < 2 ? 64 : 256; };

        agg_kernel<<<AGGB, 256>>>(stptr(0), 64, 0);
        agg_kernel<<<AGGB, 256>>>(stptr(1), 64, 1);

        int offset = 0;
        for (int step = 0; step < 4; step++) {
            int nst = 2 + step;
            if (step > 0) {
                int jn = nst - 1;
                agg_kernel<<<AGGB, 256>>>(stptr(jn), stld(jn), jn);
            }
            StepArgsM A;
            for (int j = 0; j < nst; j++) { A.h[j] = stptr(j); A.ldh[j] = stld(j); }
            for (int j = nst; j < 5; j++) { A.h[j] = stptr(0); A.ldh[j] = 64; }
            A.wfrag = wfrag + (size_t)(ci * 14 + offset) * 7 * 2048;
            A.out   = stptr(nst);
            A.nst   = nst;
            step_mma<<<GR, 256, SMEM_MMA>>>(A);
            offset += nst;
        }
    }

    // classifier: logits = pooled*cls_W[0] + s1 @ cls_W[1:] + b
    pooled_kernel<<<AGGB, 256>>>(cell1);
    LIN(cell1, 256, cls_W + 40, 40, out, 40, 256, 40, F_POOL | F_BIAS, cls_b, pooledb, cls_W);
}

// round 14
// speedup vs baseline: 1.6173x; 1.3448x over previous
#include <cuda_runtime.h>
#include <cuda_bf16.h>
#include <math.h>
#include <stdint.h>

#define NN 50000
#define EE 800000
#define NN32 (NN * 32)
#define F_STATS 1
#define F_BIAS  2
#define F_POOL  4
#define GR 391            // ceil(NN/128)

// ------------------------- static device scratch (zero-init BSS) -------------------------
__device__ float g_stem[NN * 192];
__device__ float g_cell[2][NN * 256];
__device__ float g_ab[2][NN * 64];
__device__ float g_x0[NN * 64];
__device__ float g_tmp[NN * 192];
__device__ float g_enorm[EE];
__device__ int   g_esrc[EE];
__device__ int   g_cnt[NN];
__device__ int   g_rptr[NN + 1];
__device__ int   g_fill[NN];
__device__ float g_invdeg[NN];
__device__ float g_invsqrt[NN];
__device__ float g_pooled[NN];
__device__ float g_colsum[256];
__device__ float g_colsq[256];
__device__ float g_mu[256];
__device__ float g_rsd[256];
__device__ float g_wmix[14 * 8];
// packed bf16 hi/lo planes (each u32 = 2 adjacent k-values)
__device__ uint32_t g_dh[5 * 5 * NN32];   // derived: kind 0=mean,1=sum,2=norm,3=h+sum,4=norm+x0/9
__device__ uint32_t g_dl[5 * 5 * NN32];
__device__ uint32_t g_hbh[6 * NN32];      // h slots: 0=ab0,1=ab1,2..5=cell states
__device__ uint32_t g_hbl[6 * NN32];
// fused weights in m16n8k16 B-fragment order: per lane uint4 {b0hi,b1hi,b0lo,b1lo}
__device__ uint4 g_Wfrag[28 * 7 * 32 * 32];

// ------------------------- helpers -------------------------
__device__ __forceinline__ void pack_hl(float v0, float v1, uint32_t& hi, uint32_t& lo) {
    __nv_bfloat16 h0 = __float2bfloat16_rn(v0);
    __nv_bfloat16 h1 = __float2bfloat16_rn(v1);
    float r0 = v0 - __bfloat162float(h0);
    float r1 = v1 - __bfloat162float(h1);
    __nv_bfloat16 l0 = __float2bfloat16_rn(r0);
    __nv_bfloat16 l1 = __float2bfloat16_rn(r1);
    hi = ((uint32_t)__bfloat16_as_ushort(h1) << 16) | __bfloat16_as_ushort(h0);
    lo = ((uint32_t)__bfloat16_as_ushort(l1) << 16) | __bfloat16_as_ushort(l0);
}
__device__ __forceinline__ void mma16(float (&d)[4], const uint32_t (&a)[4],
                                      uint32_t b0, uint32_t b1) {
    asm volatile("mma.sync.aligned.m16n8k16.row.col.f32.bf16.bf16.f32 "
                 "{%0,%1,%2,%3}, {%4,%5,%6,%7}, {%8,%9}, {%0,%1,%2,%3};"
                 : "+f"(d[0]), "+f"(d[1]), "+f"(d[2]), "+f"(d[3])
                 : "r"(a[0]), "r"(a[1]), "r"(a[2]), "r"(a[3]), "r"(b0), "r"(b1));
}

// ------------------------- graph preprocessing -------------------------
__global__ void zero_cnt_kernel() {
    int i = blockIdx.x * blockDim.x + threadIdx.x;
    if (i < NN) g_cnt[i] = 0;
}

__global__ void deg_kernel(const int* __restrict__ dst) {
    int e = blockIdx.x * blockDim.x + threadIdx.x;
    if (e < EE) atomicAdd(&g_cnt[dst[e]], 1);
}

__global__ void scan_kernel() {
    __shared__ int sh[1024];
    int carry = 0;
    for (int base = 0; base < NN; base += 1024) {
        int i = base + (int)threadIdx.x;
        int v = (i < NN) ? g_cnt[i] : 0;
        sh[threadIdx.x] = v;
        __syncthreads();
        for (int off = 1; off < 1024; off <<= 1) {
            int t = (threadIdx.x >= off) ? sh[threadIdx.x - off] : 0;
            __syncthreads();
            sh[threadIdx.x] += t;
            __syncthreads();
        }
        int incl = sh[threadIdx.x];
        if (i < NN) {
            int excl = carry + incl - v;
            g_rptr[i] = excl;
            g_fill[i] = excl;
            float d = (float)(v > 0 ? v : 1);
            g_invdeg[i]  = 1.0f / d;
            g_invsqrt[i] = rsqrtf(d);
        }
        carry += sh[1023];
        __syncthreads();
    }
    if (threadIdx.x == 0) g_rptr[NN] = carry;
}

__global__ void scatter_kernel(const int* __restrict__ src, const int* __restrict__ dst) {
    int e = blockIdx.x * blockDim.x + threadIdx.x;
    if (e >= EE) return;
    int s = src[e], d = dst[e];
    int pos = atomicAdd(&g_fill[d], 1);
    g_esrc[pos]  = s;
    g_enorm[pos] = g_invsqrt[s] * g_invsqrt[d];
}

// ------------------------- alpha softmax + fragment-order weight prep ----------------------
__global__ void softmax_kernel(const float* __restrict__ a) {
    int r = threadIdx.x;
    if (r >= 14) return;
    float m = -1e30f;
    for (int j = 0; j < 8; j++) m = fmaxf(m, a[r * 8 + j]);
    float e[8], s = 0.f;
    for (int j = 0; j < 8; j++) { e[j] = expf(a[r * 8 + j] - m); s += e[j]; }
    float inv = 1.f / s;
    for (int j = 0; j < 8; j++) g_wmix[r * 8 + j] = e[j] * inv;
}

__global__ void prep_kernel(const float* __restrict__ Wgcn, const float* __restrict__ Wss,
                            const float* __restrict__ Wsn,  const float* __restrict__ Wgin,
                            const float* __restrict__ Wgc1, const float* __restrict__ Wgc2,
                            const float* __restrict__ Wmlp, const float* __restrict__ Wgcnii) {
    int slot = blockIdx.x;    // ci*14 + ej
    int p    = blockIdx.y;    // pass 0..6
    int ej   = slot % 14;
    const float* wv = g_wmix + ej * 8;

    auto fused = [&](int k, int n) -> float {
        size_t in = (size_t)slot * 4096 + k * 64 + n;
        switch (p) {
            case 0:  return wv[1] * (k == n ? 1.f : 0.f) + wv[3] * Wss[in] + wv[5] * Wgc1[in];
            case 1:  return wv[3] * Wsn[in];
            case 2:  return wv[5] * Wgc2[in];
            case 3:  return wv[2] * Wgcn[in];
            case 4:  return wv[4] * Wgin[in];
            case 5:  return wv[6] * Wmlp[in];
            default: return wv[7] * 0.9f * Wgcnii[in];
        }
    };

    for (int i = 0; i < 4; i++) {
        int item = i * 256 + threadIdx.x;   // 0..1023
        int frag = item >> 5, lane = item & 31;
        int ks = frag >> 3, ntg = frag & 7;
        int g = lane >> 2, t = lane & 3;
        int n = ntg * 8 + g;
        int k0 = ks * 16 + 2 * t, k8 = k0 + 8;
        uint32_t h0, l0, h1, l1;
        pack_hl(fused(k0, n), fused(k0 + 1, n), h0, l0);
        pack_hl(fused(k8, n), fused(k8 + 1, n), h1, l1);
        g_Wfrag[((size_t)(slot * 7 + p) * 32 + frag) * 32 + lane] = make_uint4(h0, h1, l0, l1);
    }
}

// ------------------------- scalar fp32 linear (R8-proven) -------------------------
__global__ __launch_bounds__(256)
void lin_kernel(const float* __restrict__ X, int ldx,
                const float* __restrict__ W, int ldw,
                float* __restrict__ Y, int ldy,
                int K, int M, int flags,
                const float* __restrict__ bias,
                const float* __restrict__ pooled,
                const float* __restrict__ w0) {
    __shared__ __align__(16) float Xs[32 * 132];
    __shared__ __align__(16) float Ws[32 * 64];
    int tid = threadIdx.x, tx = tid & 15, ty = tid >> 4;
    int rowbase = blockIdx.x * 128, colbase = blockIdx.y * 64;
    float acc[8][4];
#pragma unroll
    for (int i = 0; i < 8; i++)
#pragma unroll
        for (int j = 0; j < 4; j++) acc[i][j] = 0.f;

    for (int kc = 0; kc < K; kc += 32) {
        __syncthreads();
#pragma unroll
        for (int i = 0; i < 2; i++) {
            int idx = i * 256 + tid;
            int kk = idx >> 4, c4 = (idx & 15) * 4;
            int gc = colbase + c4;
            float4 w4 = make_float4(0.f, 0.f, 0.f, 0.f);
            if (gc < M) w4 = *(const float4*)&W[(size_t)(kc + kk) * ldw + gc];
            *(float4*)&Ws[kk * 64 + c4] = w4;
        }
#pragma unroll
        for (int i = 0; i < 4; i++) {
            int idx = i * 256 + tid;
            int row = idx >> 3, k4 = idx & 7;
            int gr = rowbase + row;
            float4 v = make_float4(0.f, 0.f, 0.f, 0.f);
            if (gr < NN) v = *(const float4*)&X[(size_t)gr * ldx + kc + k4 * 4];
            int kb = k4 * 4;
            Xs[(kb + 0) * 132 + row] = v.x;
            Xs[(kb + 1) * 132 + row] = v.y;
            Xs[(kb + 2) * 132 + row] = v.z;
            Xs[(kb + 3) * 132 + row] = v.w;
        }
        __syncthreads();
#pragma unroll 8
        for (int k = 0; k < 32; k++) {
            float4 a0 = *(const float4*)&Xs[k * 132 + ty * 8];
            float4 a1 = *(const float4*)&Xs[k * 132 + ty * 8 + 4];
            float4 b  = *(const float4*)&Ws[k * 64 + tx * 4];
            float ar[8] = {a0.x, a0.y, a0.z, a0.w, a1.x, a1.y, a1.z, a1.w};
            float br[4] = {b.x, b.y, b.z, b.w};
#pragma unroll
            for (int i = 0; i < 8; i++)
#pragma unroll
                for (int j = 0; j < 4; j++) acc[i][j] = fmaf(ar[i], br[j], acc[i][j]);
        }
    }

    int r0 = rowbase + ty * 8, c0 = colbase + tx * 4;
#pragma unroll
    for (int i = 0; i < 8; i++) {
        int r = r0 + i;
        if (r >= NN) continue;
#pragma unroll
        for (int j = 0; j < 4; j++) {
            int c = c0 + j;
            if (c >= M) continue;
            float v = acc[i][j];
            if (flags & F_POOL) v = fmaf(pooled[r], w0[c], v);
            if (flags & F_BIAS) v += bias[c];
            Y[(size_t)r * ldy + c] = v;
        }
    }

    if (flags & F_STATS) {
        __syncthreads();
#pragma unroll
        for (int j = 0; j < 4; j++) {
            float s = 0.f, s2 = 0.f;
#pragma unroll
            for (int i = 0; i < 8; i++) {
                int r = r0 + i;
                if (r < NN) { float v = acc[i][j]; s += v; s2 = fmaf(v, v, s2); }
            }
            Xs[(tx * 4 + j) * 16 + ty] = s;
            Ws[(tx * 4 + j) * 16 + ty] = s2;
        }
        __syncthreads();
        if (tid < 64) {
            float s = 0.f, s2 = 0.f;
#pragma unroll
            for (int t = 0; t < 16; t++) { s += Xs[tid * 16 + t]; s2 += Ws[tid * 16 + t]; }
            int c = colbase + tid;
            if (c < M) { atomicAdd(&g_colsum[c], s); atomicAdd(&g_colsq[c], s2); }
        }
    }
}

// ------------------------- batch norm helpers -------------------------
__global__ void zero_stats_kernel() {
    g_colsum[threadIdx.x] = 0.f;
    g_colsq[threadIdx.x]  = 0.f;
}

__global__ void bn_fin_kernel(int M) {
    int c = threadIdx.x;
    if (c >= M) return;
    float invN = 1.f / (float)NN;
    float mu  = g_colsum[c] * invN;
    float var = g_colsq[c] * invN - mu * mu;
    g_mu[c]  = mu;
    g_rsd[c] = rsqrtf(var + 1e-5f);
}

__global__ void bn_apply_kernel(const float* __restrict__ src, float* __restrict__ dst,
                                int total4, int M, int relu,
                                uint32_t* __restrict__ bh, uint32_t* __restrict__ bl) {
    int i = blockIdx.x * blockDim.x + threadIdx.x;
    if (i >= total4) return;
    float4 v = ((const float4*)src)[i];
    int c = (i * 4) % M;
    v.x = (v.x - g_mu[c    ]) * g_rsd[c    ];
    v.y = (v.y - g_mu[c + 1]) * g_rsd[c + 1];
    v.z = (v.z - g_mu[c + 2]) * g_rsd[c + 2];
    v.w = (v.w - g_mu[c + 3]) * g_rsd[c + 3];
    if (relu) {
        v.x = fmaxf(v.x, 0.f); v.y = fmaxf(v.y, 0.f);
        v.z = fmaxf(v.z, 0.f); v.w = fmaxf(v.w, 0.f);
    }
    ((float4*)dst)[i] = v;
    if (bh) {   // M == 64: also emit packed bf16 hi/lo planes
        int row = (i * 4) / M;
        uint32_t h01, l01, h23, l23;
        pack_hl(v.x, v.y, h01, l01);
        pack_hl(v.z, v.w, h23, l23);
        size_t o = (size_t)row * 32 + (c >> 1);
        *(uint2*)&bh[o] = make_uint2(h01, h23);
        *(uint2*)&bl[o] = make_uint2(l01, l23);
    }
}

// ------------------------- CSR aggregation: writes 5 derived bf16 hi/lo planes --------------
__global__ void agg_kernel(const float* __restrict__ h, int ldh, int j) {
    int w = (blockIdx.x * blockDim.x + threadIdx.x) >> 5;
    int lane = threadIdx.x & 31;
    if (w >= NN) return;
    int beg = g_rptr[w], end = g_rptr[w + 1];
    float sx = 0.f, sy = 0.f, nx = 0.f, ny = 0.f;
    for (int e = beg; e < end; e++) {
        int s = g_esrc[e];
        float wn = g_enorm[e];
        float2 v = *(const float2*)&h[(size_t)s * ldh + lane * 2];
        sx += v.x; sy += v.y;
        nx = fmaf(wn, v.x, nx); ny = fmaf(wn, v.y, ny);
    }
    float2 hv = *(const float2*)&h[(size_t)w * ldh + lane * 2];
    float2 xv = *(const float2*)&g_x0[(size_t)w * 64 + lane * 2];
    float id = g_invdeg[w];
    size_t o = (size_t)w * 32 + lane;
    uint32_t hi, lo;
    pack_hl(sx * id, sy * id, hi, lo);
    g_dh[(0 * 5 + j) * (size_t)NN32 + o] = hi;  g_dl[(0 * 5 + j) * (size_t)NN32 + o] = lo;
    pack_hl(sx, sy, hi, lo);
    g_dh[(1 * 5 + j) * (size_t)NN32 + o] = hi;  g_dl[(1 * 5 + j) * (size_t)NN32 + o] = lo;
    pack_hl(nx, ny, hi, lo);
    g_dh[(2 * 5 + j) * (size_t)NN32 + o] = hi;  g_dl[(2 * 5 + j) * (size_t)NN32 + o] = lo;
    pack_hl(hv.x + sx, hv.y + sy, hi, lo);
    g_dh[(3 * 5 + j) * (size_t)NN32 + o] = hi;  g_dl[(3 * 5 + j) * (size_t)NN32 + o] = lo;
    pack_hl(fmaf(0.11111111f, xv.x, nx), fmaf(0.11111111f, xv.y, ny), hi, lo);
    g_dh[(4 * 5 + j) * (size_t)NN32 + o] = hi;  g_dl[(4 * 5 + j) * (size_t)NN32 + o] = lo;
}

// ------------------------- tensor-core (bf16 m16n8k16 x3) fused per-step mixed-op ----------
struct StepArgsB {
    const uint32_t* hh[5];
    const uint32_t* hl[5];
    const uint4* wfrag;      // base for this step's first slot
    float* out;              // ld 256, 64-col slice
    uint32_t* outh;          // output state hi plane
    uint32_t* outl;          // output state lo plane
    int nst;
};

#define XH_U32  (128 * 36)
#define SMEM_MMA (2 * XH_U32 * 4 + 32 * 32 * 16)

__global__ __launch_bounds__(256)
void step_mma(StepArgsB A) {
    extern __shared__ __align__(16) uint32_t smu[];
    uint32_t* Xh = smu;
    uint32_t* Xl = smu + XH_U32;
    uint4*    Wf = (uint4*)(smu + 2 * XH_U32);
    int tid = threadIdx.x, lane = tid & 31, wid = tid >> 5;
    int wm = wid & 3, wn = wid >> 2;
    int g = lane >> 2, t = lane & 3;
    int rowbase = blockIdx.x * 128;
    const int order[7] = {3, 4, 6, 5, 0, 1, 2};

    float acc[32];
#pragma unroll
    for (int i = 0; i < 32; i++) acc[i] = 0.f;

    for (int j = 0; j < A.nst; j++) {
        const uint4* wj = A.wfrag + (size_t)j * 7 * 1024;

#pragma unroll 1
        for (int oi = 0; oi < 7; oi++) {
            int p = order[oi];
            const uint32_t *sh, *sl;
            if (p == 0 || p == 5) { sh = A.hh[j]; sl = A.hl[j]; }
            else {
                int kind = (p == 6) ? 4 : (p - 1);
                sh = g_dh + (size_t)(kind * 5 + j) * NN32;
                sl = g_dl + (size_t)(kind * 5 + j) * NN32;
            }
            __syncthreads();
            {   // W fragments: straight uint4 copy
                const uint4* ws = wj + (size_t)p * 1024;
#pragma unroll
                for (int i = 0; i < 4; i++) Wf[i * 256 + tid] = ws[i * 256 + tid];
            }
            if (oi != 4) {   // oi==4 (p0) reuses oi==3's (p5) h tile
#pragma unroll
                for (int i = 0; i < 4; i++) {
                    int idx = i * 256 + tid;      // 1024 = 128 rows x 8 uint4
                    int row = idx >> 3, q = idx & 7;
                    int gr = rowbase + row;
                    uint4 vh = make_uint4(0, 0, 0, 0), vl = make_uint4(0, 0, 0, 0);
                    if (gr < NN) {
                        vh = ((const uint4*)sh)[gr * 8 + q];
                        vl = ((const uint4*)sl)[gr * 8 + q];
                    }
                    *(uint4*)&Xh[row * 36 + q * 4] = vh;
                    *(uint4*)&Xl[row * 36 + q * 4] = vl;
                }
            }
            __syncthreads();

            float pacc[32];
#pragma unroll
            for (int i = 0; i < 32; i++) pacc[i] = 0.f;

#pragma unroll
            for (int ks = 0; ks < 4; ks++) {
                uint32_t ahi[2][4], alo[2][4];
#pragma unroll
                for (int mt = 0; mt < 2; mt++) {
                    int rb = (wm * 32 + mt * 16 + g) * 36 + ks * 8 + t;
                    ahi[mt][0] = Xh[rb];
                    ahi[mt][1] = Xh[rb + 8 * 36];
                    ahi[mt][2] = Xh[rb + 4];
                    ahi[mt][3] = Xh[rb + 8 * 36 + 4];
                    alo[mt][0] = Xl[rb];
                    alo[mt][1] = Xl[rb + 8 * 36];
                    alo[mt][2] = Xl[rb + 4];
                    alo[mt][3] = Xl[rb + 8 * 36 + 4];
                }
#pragma unroll
                for (int nt = 0; nt < 4; nt++) {
                    uint4 b = Wf[(ks * 8 + wn * 4 + nt) * 32 + lane];
#pragma unroll
                    for (int mt = 0; mt < 2; mt++) {
                        float (&d)[4] = *(float (*)[4])&pacc[(mt * 4 + nt) * 4];
                        mma16(d, ahi[mt], b.x, b.y);   // hi*hi
                        mma16(d, alo[mt], b.x, b.y);   // lo*hi
                        mma16(d, ahi[mt], b.z, b.w);   // hi*lo
                    }
                }
            }
            if (oi < 4) {
#pragma unroll
                for (int i = 0; i < 32; i++) acc[i] += fmaxf(pacc[i], 0.f);
            } else {
#pragma unroll
                for (int i = 0; i < 32; i++) acc[i] += pacc[i];
            }
        }
    }

    // store: fp32 state slice + bf16 hi/lo planes for the new state
#pragma unroll
    for (int mt = 0; mt < 2; mt++)
#pragma unroll
        for (int nt = 0; nt < 4; nt++) {
            const float* a = &acc[(mt * 4 + nt) * 4];
            int row0 = rowbase + wm * 32 + mt * 16 + g;
            int col  = wn * 32 + nt * 8 + t * 2;
            size_t po = (size_t)row0 * 32 + (col >> 1);
            if (row0 < NN) {
                *(float2*)&A.out[(size_t)row0 * 256 + col] = make_float2(a[0], a[1]);
                uint32_t hi, lo;
                pack_hl(a[0], a[1], hi, lo);
                A.outh[po] = hi; A.outl[po] = lo;
            }
            int row1 = row0 + 8;
            if (row1 < NN) {
                *(float2*)&A.out[(size_t)row1 * 256 + col] = make_float2(a[2], a[3]);
                uint32_t hi, lo;
                pack_hl(a[2], a[3], hi, lo);
                size_t po1 = (size_t)row1 * 32 + (col >> 1);
                A.outh[po1] = hi; A.outl[po1] = lo;
            }
        }
}

// ------------------------- channel mean pooling -------------------------
__global__ void pooled_kernel(const float* __restrict__ h) {
    int w = (blockIdx.x * blockDim.x + threadIdx.x) >> 5;
    int lane = threadIdx.x & 31;
    if (w >= NN) return;
    const float* row = h + (size_t)w * 256;
    float s = 0.f;
#pragma unroll
    for (int i = 0; i < 8; i++) s += row[lane + i * 32];
#pragma unroll
    for (int off = 16; off > 0; off >>= 1) s += __shfl_xor_sync(0xffffffff, s, off);
    if (lane == 0) g_pooled[w] = s * (1.f / 256.f);
}

// ------------------------- host orchestration -------------------------
extern "C" void kernel_launch(void* const* d_in, const int* in_sizes, int n_in,
                              void* d_out, int out_size) {
    const float* x      = (const float*)d_in[0];
    const int*   ei     = (const int*)d_in[1];
    const float* alphas = (const float*)d_in[2];
    const float* stem_W = (const float*)d_in[3];
    const float* pre_W  = (const float*)d_in[4];
    const float* pre00  = (const float*)d_in[5];
    const float* pre10  = (const float*)d_in[6];
    const float* pre01  = (const float*)d_in[7];
    const float* pre11  = (const float*)d_in[8];
    const float* cls_W  = (const float*)d_in[17];
    const float* cls_b  = (const float*)d_in[18];
    float* out = (float*)d_out;

    float *stem, *cell, *ab, *x0p, *tmp, *pooledb;
    uint4* wfrag;
    uint32_t *hbh, *hbl;
    cudaGetSymbolAddress((void**)&stem,    g_stem);
    cudaGetSymbolAddress((void**)&cell,    g_cell);
    cudaGetSymbolAddress((void**)&ab,      g_ab);
    cudaGetSymbolAddress((void**)&x0p,     g_x0);
    cudaGetSymbolAddress((void**)&tmp,     g_tmp);
    cudaGetSymbolAddress((void**)&wfrag,   g_Wfrag);
    cudaGetSymbolAddress((void**)&pooledb, g_pooled);
    cudaGetSymbolAddress((void**)&hbh,     g_hbh);
    cudaGetSymbolAddress((void**)&hbl,     g_hbl);
    float* cell0 = cell;
    float* cell1 = cell + (size_t)NN * 256;
    float* ab0 = ab;
    float* ab1 = ab + (size_t)NN * 64;

    cudaFuncSetAttribute(step_mma, cudaFuncAttributeMaxDynamicSharedMemorySize, SMEM_MMA);

    // graph preprocessing
    zero_cnt_kernel<<<(NN + 255) / 256, 256>>>();
    deg_kernel<<<(EE + 255) / 256, 256>>>(ei + EE);
    scan_kernel<<<1, 1024>>>();
    scatter_kernel<<<(EE + 255) / 256, 256>>>(ei, ei + EE);

    // mixed-op weight prep (fused + fragment-ordered + bf16 hi/lo)
    softmax_kernel<<<1, 32>>>(alphas);
    prep_kernel<<<dim3(28, 7), 256>>>((const float*)d_in[9],  (const float*)d_in[10],
                                      (const float*)d_in[11], (const float*)d_in[12],
                                      (const float*)d_in[13], (const float*)d_in[14],
                                      (const float*)d_in[15], (const float*)d_in[16]);

    auto LIN = [&](const float* X, int ldx, const float* W, int ldw, float* Y, int ldy,
                   int K, int M, int flags, const float* bias, const float* pooled,
                   const float* w0) {
        dim3 grid(GR, (M + 63) / 64);
        lin_kernel<<<grid, 256>>>(X, ldx, W, ldw, Y, ldy, K, M, flags, bias, pooled, w0);
    };
    auto BNL = [&](const float* X, int ldx, const float* W, float* dst, int K, int M, int relu,
                   uint32_t* bh, uint32_t* bl) {
        zero_stats_kernel<<<1, 256>>>();
        LIN(X, ldx, W, M, tmp, M, K, M, F_STATS, nullptr, nullptr, nullptr);
        bn_fin_kernel<<<1, 256>>>(M);
        int t4 = NN * M / 4;
        bn_apply_kernel<<<(t4 + 255) / 256, 256>>>(tmp, dst, t4, M, relu, bh, bl);
    };

    BNL(x, 128, stem_W, stem, 128, 192, 0, nullptr, nullptr);  // stem [N,192]
    BNL(x, 128, pre_W,  x0p,  128, 64, 1, nullptr, nullptr);   // x0 [N,64]

    const int AGGB = (NN * 32 + 255) / 256;   // warp per node
    for (int ci = 0; ci < 2; ci++) {
        const float* p0 = ci ? pre01 : pre00;
        const float* p1 = ci ? pre11 : pre10;
        const float* s1p = ci ? cell0 : stem;
        int lds1 = ci ? 256 : 192;
        float* co = ci ? cell1 : cell0;

        BNL(stem, 192, p0, ab0, 192, 64, 1, hbh + 0 * (size_t)NN32, hbl + 0 * (size_t)NN32);
        BNL(s1p, lds1, p1, ab1, lds1, 64, 1, hbh + 1 * (size_t)NN32, hbl + 1 * (size_t)NN32);

        auto stptr = [&](int j) -> float* { return j == 0 ? ab0 : (j == 1 ? ab1 : co + (j - 2) * 64); };
        auto stld  = [&](int j) -> int    { return j < 2 ? 64 : 256; };

        agg_kernel<<<AGGB, 256>>>(stptr(0), 64, 0);
        agg_kernel<<<AGGB, 256>>>(stptr(1), 64, 1);

        int offset = 0;
        for (int step = 0; step < 4; step++) {
            int nst = 2 + step;
            if (step > 0) {
                int jn = nst - 1;
                agg_kernel<<<AGGB, 256>>>(stptr(jn), stld(jn), jn);
            }
            StepArgsB A;
            for (int j = 0; j < 5; j++) {
                int sj = (j < nst) ? j : 0;
                A.hh[j] = hbh + (size_t)sj * NN32;
                A.hl[j] = hbl + (size_t)sj * NN32;
            }
            A.wfrag = wfrag + (size_t)(ci * 14 + offset) * 7 * 1024;
            A.out   = stptr(nst);
            A.outh  = hbh + (size_t)nst * NN32;
            A.outl  = hbl + (size_t)nst * NN32;
            A.nst   = nst;
            step_mma<<<GR, 256, SMEM_MMA>>>(A);
            offset += nst;
        }
    }

    // classifier: logits = pooled*cls_W[0] + s1 @ cls_W[1:] + b
    pooled_kernel<<<AGGB, 256>>>(cell1);
    LIN(cell1, 256, cls_W + 40, 40, out, 40, 256, 40, F_POOL | F_BIAS, cls_b, pooledb, cls_W);
}

// round 15
// speedup vs baseline: 2.3564x; 1.4570x over previous
#include <cuda_runtime.h>
#include <cuda_bf16.h>
#include <math.h>
#include <stdint.h>

#define NN 50000
#define EE 800000
#define NN32 (NN * 32)
#define F_STATS 1
#define F_BIAS  2
#define F_POOL  4
#define GR 391            // ceil(NN/128)

// ------------------------- static device scratch (zero-init BSS) -------------------------
__device__ float g_stem[NN * 192];
__device__ float g_cell[2][NN * 256];
__device__ float g_ab[2][NN * 64];
__device__ float g_x0[NN * 64];
__device__ float g_tmp[NN * 192];
__device__ float g_enorm[EE];
__device__ int   g_esrc[EE];
__device__ int   g_cnt[NN];
__device__ int   g_rptr[NN + 1];
__device__ int   g_fill[NN];
__device__ float g_invdeg[NN];
__device__ float g_invsqrt[NN];
__device__ float g_pooled[NN];
__device__ float g_colsum[256];
__device__ float g_colsq[256];
__device__ float g_mu[256];
__device__ float g_rsd[256];
__device__ float g_wmix[14 * 8];
// packed bf16 hi/lo planes (each u32 = 2 adjacent k-values)
__device__ uint32_t g_dh[5 * 5 * NN32];   // derived: kind 0=mean,1=sum,2=norm,3=h+sum,4=norm+x0/9
__device__ uint32_t g_dl[5 * 5 * NN32];
__device__ uint32_t g_hbh[6 * NN32];      // h slots: 0=ab0,1=ab1,2..5=cell states
__device__ uint32_t g_hbl[6 * NN32];
// fused weights in m16n8k16 B-fragment order: per lane uint4 {b0hi,b1hi,b0lo,b1lo}
__device__ uint4 g_Wfrag[28 * 7 * 32 * 32];

// ------------------------- helpers -------------------------
__device__ __forceinline__ void pack_hl(float v0, float v1, uint32_t& hi, uint32_t& lo) {
    __nv_bfloat16 h0 = __float2bfloat16_rn(v0);
    __nv_bfloat16 h1 = __float2bfloat16_rn(v1);
    float r0 = v0 - __bfloat162float(h0);
    float r1 = v1 - __bfloat162float(h1);
    __nv_bfloat16 l0 = __float2bfloat16_rn(r0);
    __nv_bfloat16 l1 = __float2bfloat16_rn(r1);
    hi = ((uint32_t)__bfloat16_as_ushort(h1) << 16) | __bfloat16_as_ushort(h0);
    lo = ((uint32_t)__bfloat16_as_ushort(l1) << 16) | __bfloat16_as_ushort(l0);
}
__device__ __forceinline__ void mma16(float (&d)[4], const uint32_t (&a)[4],
                                      uint32_t b0, uint32_t b1) {
    asm volatile("mma.sync.aligned.m16n8k16.row.col.f32.bf16.bf16.f32 "
                 "{%0,%1,%2,%3}, {%4,%5,%6,%7}, {%8,%9}, {%0,%1,%2,%3};"
                 : "+f"(d[0]), "+f"(d[1]), "+f"(d[2]), "+f"(d[3])
                 : "r"(a[0]), "r"(a[1]), "r"(a[2]), "r"(a[3]), "r"(b0), "r"(b1));
}
__device__ __forceinline__ void cpa16(uint32_t dst, const void* src, int sz) {
    asm volatile("cp.async.cg.shared.global [%0], [%1], 16, %2;"
                 :: "r"(dst), "l"(src), "r"(sz) : "memory");
}
__device__ __forceinline__ void cpa_commit() {
    asm volatile("cp.async.commit_group;" ::: "memory");
}
template <int N>
__device__ __forceinline__ void cpa_wait() {
    asm volatile("cp.async.wait_group %0;" :: "n"(N) : "memory");
}

// ------------------------- graph preprocessing -------------------------
__global__ void zero_cnt_kernel() {
    int i = blockIdx.x * blockDim.x + threadIdx.x;
    if (i < NN) g_cnt[i] = 0;
}

__global__ void deg_kernel(const int* __restrict__ dst) {
    int e = blockIdx.x * blockDim.x + threadIdx.x;
    if (e < EE) atomicAdd(&g_cnt[dst[e]], 1);
}

__global__ void scan_kernel() {
    __shared__ int sh[1024];
    int carry = 0;
    for (int base = 0; base < NN; base += 1024) {
        int i = base + (int)threadIdx.x;
        int v = (i < NN) ? g_cnt[i] : 0;
        sh[threadIdx.x] = v;
        __syncthreads();
        for (int off = 1; off < 1024; off <<= 1) {
            int t = (threadIdx.x >= off) ? sh[threadIdx.x - off] : 0;
            __syncthreads();
            sh[threadIdx.x] += t;
            __syncthreads();
        }
        int incl = sh[threadIdx.x];
        if (i < NN) {
            int excl = carry + incl - v;
            g_rptr[i] = excl;
            g_fill[i] = excl;
            float d = (float)(v > 0 ? v : 1);
            g_invdeg[i]  = 1.0f / d;
            g_invsqrt[i] = rsqrtf(d);
        }
        carry += sh[1023];
        __syncthreads();
    }
    if (threadIdx.x == 0) g_rptr[NN] = carry;
}

__global__ void scatter_kernel(const int* __restrict__ src, const int* __restrict__ dst) {
    int e = blockIdx.x * blockDim.x + threadIdx.x;
    if (e >= EE) return;
    int s = src[e], d = dst[e];
    int pos = atomicAdd(&g_fill[d], 1);
    g_esrc[pos]  = s;
    g_enorm[pos] = g_invsqrt[s] * g_invsqrt[d];
}

// ------------------------- alpha softmax + fragment-order weight prep ----------------------
__global__ void softmax_kernel(const float* __restrict__ a) {
    int r = threadIdx.x;
    if (r >= 14) return;
    float m = -1e30f;
    for (int j = 0; j < 8; j++) m = fmaxf(m, a[r * 8 + j]);
    float e[8], s = 0.f;
    for (int j = 0; j < 8; j++) { e[j] = expf(a[r * 8 + j] - m); s += e[j]; }
    float inv = 1.f / s;
    for (int j = 0; j < 8; j++) g_wmix[r * 8 + j] = e[j] * inv;
}

__global__ void prep_kernel(const float* __restrict__ Wgcn, const float* __restrict__ Wss,
                            const float* __restrict__ Wsn,  const float* __restrict__ Wgin,
                            const float* __restrict__ Wgc1, const float* __restrict__ Wgc2,
                            const float* __restrict__ Wmlp, const float* __restrict__ Wgcnii) {
    int slot = blockIdx.x;    // ci*14 + ej
    int p    = blockIdx.y;    // pass 0..6
    int ej   = slot % 14;
    const float* wv = g_wmix + ej * 8;

    auto fused = [&](int k, int n) -> float {
        size_t in = (size_t)slot * 4096 + k * 64 + n;
        switch (p) {
            case 0:  return wv[1] * (k == n ? 1.f : 0.f) + wv[3] * Wss[in] + wv[5] * Wgc1[in];
            case 1:  return wv[3] * Wsn[in];
            case 2:  return wv[5] * Wgc2[in];
            case 3:  return wv[2] * Wgcn[in];
            case 4:  return wv[4] * Wgin[in];
            case 5:  return wv[6] * Wmlp[in];
            default: return wv[7] * 0.9f * Wgcnii[in];
        }
    };

    for (int i = 0; i < 4; i++) {
        int item = i * 256 + threadIdx.x;   // 0..1023
        int frag = item >> 5, lane = item & 31;
        int ks = frag >> 3, ntg = frag & 7;
        int g = lane >> 2, t = lane & 3;
        int n = ntg * 8 + g;
        int k0 = ks * 16 + 2 * t, k8 = k0 + 8;
        uint32_t h0, l0, h1, l1;
        pack_hl(fused(k0, n), fused(k0 + 1, n), h0, l0);
        pack_hl(fused(k8, n), fused(k8 + 1, n), h1, l1);
        g_Wfrag[((size_t)(slot * 7 + p) * 32 + frag) * 32 + lane] = make_uint4(h0, h1, l0, l1);
    }
}

// ------------------------- scalar fp32 linear (R8-proven) -------------------------
__global__ __launch_bounds__(256)
void lin_kernel(const float* __restrict__ X, int ldx,
                const float* __restrict__ W, int ldw,
                float* __restrict__ Y, int ldy,
                int K, int M, int flags,
                const float* __restrict__ bias,
                const float* __restrict__ pooled,
                const float* __restrict__ w0) {
    __shared__ __align__(16) float Xs[32 * 132];
    __shared__ __align__(16) float Ws[32 * 64];
    int tid = threadIdx.x, tx = tid & 15, ty = tid >> 4;
    int rowbase = blockIdx.x * 128, colbase = blockIdx.y * 64;
    float acc[8][4];
#pragma unroll
    for (int i = 0; i < 8; i++)
#pragma unroll
        for (int j = 0; j < 4; j++) acc[i][j] = 0.f;

    for (int kc = 0; kc < K; kc += 32) {
        __syncthreads();
#pragma unroll
        for (int i = 0; i < 2; i++) {
            int idx = i * 256 + tid;
            int kk = idx >> 4, c4 = (idx & 15) * 4;
            int gc = colbase + c4;
            float4 w4 = make_float4(0.f, 0.f, 0.f, 0.f);
            if (gc < M) w4 = *(const float4*)&W[(size_t)(kc + kk) * ldw + gc];
            *(float4*)&Ws[kk * 64 + c4] = w4;
        }
#pragma unroll
        for (int i = 0; i < 4; i++) {
            int idx = i * 256 + tid;
            int row = idx >> 3, k4 = idx & 7;
            int gr = rowbase + row;
            float4 v = make_float4(0.f, 0.f, 0.f, 0.f);
            if (gr < NN) v = *(const float4*)&X[(size_t)gr * ldx + kc + k4 * 4];
            int kb = k4 * 4;
            Xs[(kb + 0) * 132 + row] = v.x;
            Xs[(kb + 1) * 132 + row] = v.y;
            Xs[(kb + 2) * 132 + row] = v.z;
            Xs[(kb + 3) * 132 + row] = v.w;
        }
        __syncthreads();
#pragma unroll 8
        for (int k = 0; k < 32; k++) {
            float4 a0 = *(const float4*)&Xs[k * 132 + ty * 8];
            float4 a1 = *(const float4*)&Xs[k * 132 + ty * 8 + 4];
            float4 b  = *(const float4*)&Ws[k * 64 + tx * 4];
            float ar[8] = {a0.x, a0.y, a0.z, a0.w, a1.x, a1.y, a1.z, a1.w};
            float br[4] = {b.x, b.y, b.z, b.w};
#pragma unroll
            for (int i = 0; i < 8; i++)
#pragma unroll
                for (int j = 0; j < 4; j++) acc[i][j] = fmaf(ar[i], br[j], acc[i][j]);
        }
    }

    int r0 = rowbase + ty * 8, c0 = colbase + tx * 4;
#pragma unroll
    for (int i = 0; i < 8; i++) {
        int r = r0 + i;
        if (r >= NN) continue;
#pragma unroll
        for (int j = 0; j < 4; j++) {
            int c = c0 + j;
            if (c >= M) continue;
            float v = acc[i][j];
            if (flags & F_POOL) v = fmaf(pooled[r], w0[c], v);
            if (flags & F_BIAS) v += bias[c];
            Y[(size_t)r * ldy + c] = v;
        }
    }

    if (flags & F_STATS) {
        __syncthreads();
#pragma unroll
        for (int j = 0; j < 4; j++) {
            float s = 0.f, s2 = 0.f;
#pragma unroll
            for (int i = 0; i < 8; i++) {
                int r = r0 + i;
                if (r < NN) { float v = acc[i][j]; s += v; s2 = fmaf(v, v, s2); }
            }
            Xs[(tx * 4 + j) * 16 + ty] = s;
            Ws[(tx * 4 + j) * 16 + ty] = s2;
        }
        __syncthreads();
        if (tid < 64) {
            float s = 0.f, s2 = 0.f;
#pragma unroll
            for (int t = 0; t < 16; t++) { s += Xs[tid * 16 + t]; s2 += Ws[tid * 16 + t]; }
            int c = colbase + tid;
            if (c < M) { atomicAdd(&g_colsum[c], s); atomicAdd(&g_colsq[c], s2); }
        }
    }
}

// ------------------------- batch norm helpers -------------------------
__global__ void zero_stats_kernel() {
    g_colsum[threadIdx.x] = 0.f;
    g_colsq[threadIdx.x]  = 0.f;
}

__global__ void bn_fin_kernel(int M) {
    int c = threadIdx.x;
    if (c >= M) return;
    float invN = 1.f / (float)NN;
    float mu  = g_colsum[c] * invN;
    float var = g_colsq[c] * invN - mu * mu;
    g_mu[c]  = mu;
    g_rsd[c] = rsqrtf(var + 1e-5f);
}

__global__ void bn_apply_kernel(const float* __restrict__ src, float* __restrict__ dst,
                                int total4, int M, int relu,
                                uint32_t* __restrict__ bh, uint32_t* __restrict__ bl) {
    int i = blockIdx.x * blockDim.x + threadIdx.x;
    if (i >= total4) return;
    float4 v = ((const float4*)src)[i];
    int c = (i * 4) % M;
    v.x = (v.x - g_mu[c    ]) * g_rsd[c    ];
    v.y = (v.y - g_mu[c + 1]) * g_rsd[c + 1];
    v.z = (v.z - g_mu[c + 2]) * g_rsd[c + 2];
    v.w = (v.w - g_mu[c + 3]) * g_rsd[c + 3];
    if (relu) {
        v.x = fmaxf(v.x, 0.f); v.y = fmaxf(v.y, 0.f);
        v.z = fmaxf(v.z, 0.f); v.w = fmaxf(v.w, 0.f);
    }
    ((float4*)dst)[i] = v;
    if (bh) {   // M == 64: also emit packed bf16 hi/lo planes
        int row = (i * 4) / M;
        uint32_t h01, l01, h23, l23;
        pack_hl(v.x, v.y, h01, l01);
        pack_hl(v.z, v.w, h23, l23);
        size_t o = (size_t)row * 32 + (c >> 1);
        *(uint2*)&bh[o] = make_uint2(h01, h23);
        *(uint2*)&bl[o] = make_uint2(l01, l23);
    }
}

// ------------------------- CSR aggregation: writes 5 derived bf16 hi/lo planes --------------
__global__ void agg_kernel(const float* __restrict__ h, int ldh, int j) {
    int w = (blockIdx.x * blockDim.x + threadIdx.x) >> 5;
    int lane = threadIdx.x & 31;
    if (w >= NN) return;
    int beg = g_rptr[w], end = g_rptr[w + 1];
    float sx = 0.f, sy = 0.f, nx = 0.f, ny = 0.f;
    for (int e = beg; e < end; e++) {
        int s = g_esrc[e];
        float wn = g_enorm[e];
        float2 v = *(const float2*)&h[(size_t)s * ldh + lane * 2];
        sx += v.x; sy += v.y;
        nx = fmaf(wn, v.x, nx); ny = fmaf(wn, v.y, ny);
    }
    float2 hv = *(const float2*)&h[(size_t)w * ldh + lane * 2];
    float2 xv = *(const float2*)&g_x0[(size_t)w * 64 + lane * 2];
    float id = g_invdeg[w];
    size_t o = (size_t)w * 32 + lane;
    uint32_t hi, lo;
    pack_hl(sx * id, sy * id, hi, lo);
    g_dh[(0 * 5 + j) * (size_t)NN32 + o] = hi;  g_dl[(0 * 5 + j) * (size_t)NN32 + o] = lo;
    pack_hl(sx, sy, hi, lo);
    g_dh[(1 * 5 + j) * (size_t)NN32 + o] = hi;  g_dl[(1 * 5 + j) * (size_t)NN32 + o] = lo;
    pack_hl(nx, ny, hi, lo);
    g_dh[(2 * 5 + j) * (size_t)NN32 + o] = hi;  g_dl[(2 * 5 + j) * (size_t)NN32 + o] = lo;
    pack_hl(hv.x + sx, hv.y + sy, hi, lo);
    g_dh[(3 * 5 + j) * (size_t)NN32 + o] = hi;  g_dl[(3 * 5 + j) * (size_t)NN32 + o] = lo;
    pack_hl(fmaf(0.11111111f, xv.x, nx), fmaf(0.11111111f, xv.y, ny), hi, lo);
    g_dh[(4 * 5 + j) * (size_t)NN32 + o] = hi;  g_dl[(4 * 5 + j) * (size_t)NN32 + o] = lo;
}

// ------------------------- tensor-core (bf16 m16n8k16 x3) pipelined per-step mixed-op ------
struct StepArgsB {
    const uint32_t* hh[5];
    const uint32_t* hl[5];
    const uint4* wfrag;      // base for this step's first slot
    float* out;              // ld 256, 64-col slice
    uint32_t* outh;          // output state hi plane
    uint32_t* outl;          // output state lo plane
    int nst;
};

// smem layout (u32 units): Xbuf[2][9216] (hi 4608 | lo 4608), Wbuf[2][4096]
#define XBUF_U32 9216
#define WOFF_U32 (2 * XBUF_U32)
#define WBUF_U32 4096
#define SMEM_MMA ((WOFF_U32 + 2 * WBUF_U32) * 4)

__global__ __launch_bounds__(256)
void step_mma(StepArgsB A) {
    extern __shared__ __align__(16) uint32_t smu[];
    uint32_t sb;
    asm("{ .reg .u64 t; cvta.to.shared.u64 t, %1; cvt.u32.u64 %0, t; }" : "=r"(sb) : "l"(smu));
    int tid = threadIdx.x, lane = tid & 31, wid = tid >> 5;
    int wm = wid & 3, wn = wid >> 2;
    int g = lane >> 2, t = lane & 3;
    int rowbase = blockIdx.x * 128;
    int np = A.nst * 7;

    float acc[32];
#pragma unroll
    for (int i = 0; i < 32; i++) acc[i] = 0.f;

    // per-thread constant pieces for the prefetch
    int prow[4], pq[4], psz[4];
    const uint32_t pbyte0 = (uint32_t)((tid >> 3) * 144 + (tid & 7) * 16);
    (void)pbyte0;
#pragma unroll
    for (int i = 0; i < 4; i++) {
        int idx = i * 256 + tid;
        prow[i] = idx >> 3;
        pq[i]   = idx & 7;
        int gr = rowbase + prow[i];
        psz[i]  = (gr < NN) ? 16 : 0;
    }

    auto prefetch = [&](int pass, int buf) {
        int j = pass / 7, p = pass % 7;
        const uint32_t *sh, *sl;
        if (p == 0 || p == 5) { sh = A.hh[j]; sl = A.hl[j]; }
        else {
            int kind = (p == 6) ? 4 : (p - 1);
            sh = g_dh + (size_t)(kind * 5 + j) * NN32;
            sl = g_dl + (size_t)(kind * 5 + j) * NN32;
        }
        uint32_t xb = sb + buf * (XBUF_U32 * 4);
#pragma unroll
        for (int i = 0; i < 4; i++) {
            int gr = rowbase + prow[i];
            int grc = (gr < NN) ? gr : 0;
            size_t sbyte = (size_t)grc * 128 + pq[i] * 16;
            uint32_t dbyte = (uint32_t)(prow[i] * 144 + pq[i] * 16);
            cpa16(xb + dbyte, (const char*)sh + sbyte, psz[i]);
            cpa16(xb + 4608 * 4 + dbyte, (const char*)sl + sbyte, psz[i]);
        }
        const uint4* ws = A.wfrag + ((size_t)j * 7 + p) * 1024;
        uint32_t wb = sb + (WOFF_U32 + buf * WBUF_U32) * 4;
#pragma unroll
        for (int i = 0; i < 4; i++) {
            int idx = i * 256 + tid;
            cpa16(wb + idx * 16, ws + idx, 16);
        }
        cpa_commit();
    };

    prefetch(0, 0);

#pragma unroll 1
    for (int pass = 0; pass < np; pass++) {
        int buf = pass & 1;
        if (pass + 1 < np) {
            prefetch(pass + 1, buf ^ 1);
            cpa_wait<1>();
        } else {
            cpa_wait<0>();
        }
        __syncthreads();

        const uint32_t* Xh = smu + buf * XBUF_U32;
        const uint32_t* Xl = Xh + 4608;
        const uint4*    Wf = (const uint4*)(smu + WOFF_U32 + buf * WBUF_U32);
        int p = pass % 7;
        bool isrelu = (p >= 3);

        if (isrelu) {
            float pacc[32];
#pragma unroll
            for (int i = 0; i < 32; i++) pacc[i] = 0.f;
#pragma unroll
            for (int ks = 0; ks < 4; ks++) {
                uint32_t ahi[2][4], alo[2][4];
#pragma unroll
                for (int mt = 0; mt < 2; mt++) {
                    int rb = (wm * 32 + mt * 16 + g) * 36 + ks * 8 + t;
                    ahi[mt][0] = Xh[rb];
                    ahi[mt][1] = Xh[rb + 8 * 36];
                    ahi[mt][2] = Xh[rb + 4];
                    ahi[mt][3] = Xh[rb + 8 * 36 + 4];
                    alo[mt][0] = Xl[rb];
                    alo[mt][1] = Xl[rb + 8 * 36];
                    alo[mt][2] = Xl[rb + 4];
                    alo[mt][3] = Xl[rb + 8 * 36 + 4];
                }
#pragma unroll
                for (int nt = 0; nt < 4; nt++) {
                    uint4 b = Wf[(ks * 8 + wn * 4 + nt) * 32 + lane];
#pragma unroll
                    for (int mt = 0; mt < 2; mt++) {
                        float (&d)[4] = *(float (*)[4])&pacc[(mt * 4 + nt) * 4];
                        mma16(d, ahi[mt], b.x, b.y);
                        mma16(d, alo[mt], b.x, b.y);
                        mma16(d, ahi[mt], b.z, b.w);
                    }
                }
            }
#pragma unroll
            for (int i = 0; i < 32; i++) acc[i] += fmaxf(pacc[i], 0.f);
        } else {
#pragma unroll
            for (int ks = 0; ks < 4; ks++) {
                uint32_t ahi[2][4], alo[2][4];
#pragma unroll
                for (int mt = 0; mt < 2; mt++) {
                    int rb = (wm * 32 + mt * 16 + g) * 36 + ks * 8 + t;
                    ahi[mt][0] = Xh[rb];
                    ahi[mt][1] = Xh[rb + 8 * 36];
                    ahi[mt][2] = Xh[rb + 4];
                    ahi[mt][3] = Xh[rb + 8 * 36 + 4];
                    alo[mt][0] = Xl[rb];
                    alo[mt][1] = Xl[rb + 8 * 36];
                    alo[mt][2] = Xl[rb + 4];
                    alo[mt][3] = Xl[rb + 8 * 36 + 4];
                }
#pragma unroll
                for (int nt = 0; nt < 4; nt++) {
                    uint4 b = Wf[(ks * 8 + wn * 4 + nt) * 32 + lane];
#pragma unroll
                    for (int mt = 0; mt < 2; mt++) {
                        float (&d)[4] = *(float (*)[4])&acc[(mt * 4 + nt) * 4];
                        mma16(d, ahi[mt], b.x, b.y);
                        mma16(d, alo[mt], b.x, b.y);
                        mma16(d, ahi[mt], b.z, b.w);
                    }
                }
            }
        }
        __syncthreads();   // all warps done with buf before it is refilled at pass+2
    }

    // store: fp32 state slice + bf16 hi/lo planes for the new state
#pragma unroll
    for (int mt = 0; mt < 2; mt++)
#pragma unroll
        for (int nt = 0; nt < 4; nt++) {
            const float* a = &acc[(mt * 4 + nt) * 4];
            int row0 = rowbase + wm * 32 + mt * 16 + g;
            int col  = wn * 32 + nt * 8 + t * 2;
            if (row0 < NN) {
                *(float2*)&A.out[(size_t)row0 * 256 + col] = make_float2(a[0], a[1]);
                uint32_t hi, lo;
                pack_hl(a[0], a[1], hi, lo);
                size_t po = (size_t)row0 * 32 + (col >> 1);
                A.outh[po] = hi; A.outl[po] = lo;
            }
            int row1 = row0 + 8;
            if (row1 < NN) {
                *(float2*)&A.out[(size_t)row1 * 256 + col] = make_float2(a[2], a[3]);
                uint32_t hi, lo;
                pack_hl(a[2], a[3], hi, lo);
                size_t po1 = (size_t)row1 * 32 + (col >> 1);
                A.outh[po1] = hi; A.outl[po1] = lo;
            }
        }
}

// ------------------------- channel mean pooling -------------------------
__global__ void pooled_kernel(const float* __restrict__ h) {
    int w = (blockIdx.x * blockDim.x + threadIdx.x) >> 5;
    int lane = threadIdx.x & 31;
    if (w >= NN) return;
    const float* row = h + (size_t)w * 256;
    float s = 0.f;
#pragma unroll
    for (int i = 0; i < 8; i++) s += row[lane + i * 32];
#pragma unroll
    for (int off = 16; off > 0; off >>= 1) s += __shfl_xor_sync(0xffffffff, s, off);
    if (lane == 0) g_pooled[w] = s * (1.f / 256.f);
}

// ------------------------- host orchestration -------------------------
extern "C" void kernel_launch(void* const* d_in, const int* in_sizes, int n_in,
                              void* d_out, int out_size) {
    const float* x      = (const float*)d_in[0];
    const int*   ei     = (const int*)d_in[1];
    const float* alphas = (const float*)d_in[2];
    const float* stem_W = (const float*)d_in[3];
    const float* pre_W  = (const float*)d_in[4];
    const float* pre00  = (const float*)d_in[5];
    const float* pre10  = (const float*)d_in[6];
    const float* pre01  = (const float*)d_in[7];
    const float* pre11  = (const float*)d_in[8];
    const float* cls_W  = (const float*)d_in[17];
    const float* cls_b  = (const float*)d_in[18];
    float* out = (float*)d_out;

    float *stem, *cell, *ab, *x0p, *tmp, *pooledb;
    uint4* wfrag;
    uint32_t *hbh, *hbl;
    cudaGetSymbolAddress((void**)&stem,    g_stem);
    cudaGetSymbolAddress((void**)&cell,    g_cell);
    cudaGetSymbolAddress((void**)&ab,      g_ab);
    cudaGetSymbolAddress((void**)&x0p,     g_x0);
    cudaGetSymbolAddress((void**)&tmp,     g_tmp);
    cudaGetSymbolAddress((void**)&wfrag,   g_Wfrag);
    cudaGetSymbolAddress((void**)&pooledb, g_pooled);
    cudaGetSymbolAddress((void**)&hbh,     g_hbh);
    cudaGetSymbolAddress((void**)&hbl,     g_hbl);
    float* cell0 = cell;
    float* cell1 = cell + (size_t)NN * 256;
    float* ab0 = ab;
    float* ab1 = ab + (size_t)NN * 64;

    cudaFuncSetAttribute(step_mma, cudaFuncAttributeMaxDynamicSharedMemorySize, SMEM_MMA);

    // graph preprocessing
    zero_cnt_kernel<<<(NN + 255) / 256, 256>>>();
    deg_kernel<<<(EE + 255) / 256, 256>>>(ei + EE);
    scan_kernel<<<1, 1024>>>();
    scatter_kernel<<<(EE + 255) / 256, 256>>>(ei, ei + EE);

    // mixed-op weight prep (fused + fragment-ordered + bf16 hi/lo)
    softmax_kernel<<<1, 32>>>(alphas);
    prep_kernel<<<dim3(28, 7), 256>>>((const float*)d_in[9],  (const float*)d_in[10],
                                      (const float*)d_in[11], (const float*)d_in[12],
                                      (const float*)d_in[13], (const float*)d_in[14],
                                      (const float*)d_in[15], (const float*)d_in[16]);

    auto LIN = [&](const float* X, int ldx, const float* W, int ldw, float* Y, int ldy,
                   int K, int M, int flags, const float* bias, const float* pooled,
                   const float* w0) {
        dim3 grid(GR, (M + 63) / 64);
        lin_kernel<<<grid, 256>>>(X, ldx, W, ldw, Y, ldy, K, M, flags, bias, pooled, w0);
    };
    auto BNL = [&](const float* X, int ldx, const float* W, float* dst, int K, int M, int relu,
                   uint32_t* bh, uint32_t* bl) {
        zero_stats_kernel<<<1, 256>>>();
        LIN(X, ldx, W, M, tmp, M, K, M, F_STATS, nullptr, nullptr, nullptr);
        bn_fin_kernel<<<1, 256>>>(M);
        int t4 = NN * M / 4;
        bn_apply_kernel<<<(t4 + 255) / 256, 256>>>(tmp, dst, t4, M, relu, bh, bl);
    };

    BNL(x, 128, stem_W, stem, 128, 192, 0, nullptr, nullptr);  // stem [N,192]
    BNL(x, 128, pre_W,  x0p,  128, 64, 1, nullptr, nullptr);   // x0 [N,64]

    const int AGGB = (NN * 32 + 255) / 256;   // warp per node
    for (int ci = 0; ci < 2; ci++) {
        const float* p0 = ci ? pre01 : pre00;
        const float* p1 = ci ? pre11 : pre10;
        const float* s1p = ci ? cell0 : stem;
        int lds1 = ci ? 256 : 192;
        float* co = ci ? cell1 : cell0;

        BNL(stem, 192, p0, ab0, 192, 64, 1, hbh + 0 * (size_t)NN32, hbl + 0 * (size_t)NN32);
        BNL(s1p, lds1, p1, ab1, lds1, 64, 1, hbh + 1 * (size_t)NN32, hbl + 1 * (size_t)NN32);

        auto stptr = [&](int j) -> float* { return j == 0 ? ab0 : (j == 1 ? ab1 : co + (j - 2) * 64); };
        auto stld  = [&](int j) -> int    { return j < 2 ? 64 : 256; };

        agg_kernel<<<AGGB, 256>>>(stptr(0), 64, 0);
        agg_kernel<<<AGGB, 256>>>(stptr(1), 64, 1);

        int offset = 0;
        for (int step = 0; step < 4; step++) {
            int nst = 2 + step;
            if (step > 0) {
                int jn = nst - 1;
                agg_kernel<<<AGGB, 256>>>(stptr(jn), stld(jn), jn);
            }
            StepArgsB A;
            for (int j = 0; j < 5; j++) {
                int sj = (j < nst) ? j : 0;
                A.hh[j] = hbh + (size_t)sj * NN32;
                A.hl[j] = hbl + (size_t)sj * NN32;
            }
            A.wfrag = wfrag + (size_t)(ci * 14 + offset) * 7 * 1024;
            A.out   = stptr(nst);
            A.outh  = hbh + (size_t)nst * NN32;
            A.outl  = hbl + (size_t)nst * NN32;
            A.nst   = nst;
            step_mma<<<GR, 256, SMEM_MMA>>>(A);
            offset += nst;
        }
    }

    // classifier: logits = pooled*cls_W[0] + s1 @ cls_W[1:] + b
    pooled_kernel<<<AGGB, 256>>>(cell1);
    LIN(cell1, 256, cls_W + 40, 40, out, 40, 256, 40, F_POOL | F_BIAS, cls_b, pooledb, cls_W);
}